// round 10
// baseline (speedup 1.0000x reference)
#include <cuda_runtime.h>
#include <cfloat>

#define Nn 20000
#define Ee 320000
#define Gg 64
#define D0 16
#define Hh 32
#define NK 33
#define EPSI 1e-5f
#define FULL 0xffffffffu
#define EDGE_BLKS ((Ee+255)/256)      /* 1250 */
#define AGG_BLKS  (Nn/8)              /* 2500 (general-path PQ grids) */

// ---------------- static device scratch (zero-init at load; self-cleaning across replays) ----------------
__device__ float g_A0[NK*D0*Hh], g_B0[NK*D0*Hh];
__device__ float g_A1[NK*Hh*Hh], g_B1[NK*Hh*Hh];
__device__ unsigned char g_k0[Ee], g_k1[Ee];
__device__ int g_hist[2*NK];            // zeroed by k_mlp each run
__device__ int g_deg[Nn];               // zeroed by k_alloc after read
__device__ int g_total;                 // zeroed by k_mlp each run
__device__ int g_off[Nn], g_end[Nn], g_cur[Nn];
__device__ int g_nlive[2], g_klive[2];
__device__ uint2 g_ebuf[Ee];            // CSR-ordered packed payload
__device__ __align__(16) float g_PQ[(size_t)NK*Nn*64];   // general path only
__device__ __align__(16) float g_h[Nn*Hh], g_hn[Nn*Hh];
__device__ float g_stats[4*Hh];         // [sum0|sq0|sum1|sq1], zeroed by k_pre block 0
__device__ float g_pool[Gg*Hh];
__device__ int   g_pcnt[Gg];

__device__ __forceinline__ void rank32(float wj, float bj, float& t, int& r, int j){
    t = (wj != 0.0f) ? (-bj / wj) : FLT_MAX;
    r = 0;
    #pragma unroll
    for (int m = 0; m < 32; m++){
        float tm = __shfl_sync(FULL, t, m);
        r += (tm < t || (tm == t && m < j));
    }
}

// static-component broadcast of float4 element i%4 from lane i/4 (i compile-time)
#define BCAST4(vec, i) __shfl_sync(FULL, ((i)&3)==0 ? (vec).x : ((i)&3)==1 ? (vec).y : ((i)&3)==2 ? (vec).z : (vec).w, (i)>>2)

// ==== fused: blocks [0,2*NK) buildAB, blocks [2*NK,...) per-edge interval/hist/deg ====
__global__ void __launch_bounds__(256)
k_pre(const float* attr, const int* dst,
      const float* ew1a, const float* eb1a, const float* ew2a, const float* eb2a,
      const float* ew1b, const float* eb1b, const float* ew2b, const float* eb2b){
    int t = threadIdx.x;
    if (blockIdx.x < 2*NK){
        if (blockIdx.x == 0){
            for (int i = t; i < 4*Hh; i += 256) g_stats[i] = 0.f;
            for (int i = t; i < Gg*Hh; i += 256) g_pool[i] = 0.f;
            if (t < Gg) g_pcnt[t] = 0;
        }
        int layer = (blockIdx.x >= NK);
        int k = blockIdx.x - layer*NK;
        int D = layer ? (Hh*Hh) : (D0*Hh);
        float* A = layer ? g_A1 : g_A0;
        float* B = layer ? g_B1 : g_B0;
        const float* ew1 = layer ? ew1b : ew1a;
        const float* eb1 = layer ? eb1b : eb1a;
        const float* ew2 = layer ? ew2b : ew2a;
        const float* eb2 = layer ? eb2b : eb2a;
        __shared__ float sw[32], sb[32]; __shared__ int sr[32];
        if (t < 32){
            float wj = ew1[t], bj = eb1[t], tv; int r;
            rank32(wj, bj, tv, r, t);
            sw[t]=wj; sb[t]=bj; sr[t]=r;
        }
        __syncthreads();
        for (int d = t; d < D; d += 256){
            float a = 0.f, b = eb2[d];
            for (int j=0;j<32;j++){
                float wj = sw[j];
                bool act = (wj > 0.f) ? (k > sr[j]) : ((wj < 0.f) ? (k <= sr[j]) : (sb[j] > 0.f));
                if (act){ float w2 = ew2[j*D+d]; a += wj*w2; b += sb[j]*w2; }
            }
            A[k*D+d]=a; B[k*D+d]=b;
        }
        return;
    }
    // ---- edge role ----
    __shared__ float st0[32], st1[32];
    __shared__ int sh[2*NK];
    int lane = t & 31;
    if (t < 32){ float tv; int r; rank32(ew1a[t], eb1a[t], tv, r, t); st0[r]=tv; }
    else if (t < 64){ int j=t-32; float tv; int r; rank32(ew1b[j], eb1b[j], tv, r, j); st1[r]=tv; }
    if (t < 2*NK) sh[t] = 0;
    __syncthreads();
    int e = (blockIdx.x - 2*NK)*256 + t;
    bool valid = (e < Ee);
    float a = valid ? attr[e] : -FLT_MAX;
    int k0 = 0, k1 = 0;
    #pragma unroll
    for (int step = 16; step > 0; step >>= 1){
        if (st0[k0 + step - 1] <= a) k0 += step;
        if (st1[k1 + step - 1] <= a) k1 += step;
    }
    k0 += (st0[k0] <= a);   // counts range [0,32]
    k1 += (st1[k1] <= a);
    if (valid){
        g_k0[e]=(unsigned char)k0; g_k1[e]=(unsigned char)k1;
        atomicAdd(&g_deg[dst[e]],1);
    }
    int key0 = valid ? k0 : -1;
    unsigned m0 = __match_any_sync(FULL, key0);
    if (valid && lane == (__ffs(m0)-1)) atomicAdd(&sh[k0], __popc(m0));
    int key1 = valid ? k1 : -1;
    unsigned m1 = __match_any_sync(FULL, key1);
    if (valid && lane == (__ffs(m1)-1)) atomicAdd(&sh[NK+k1], __popc(m1));
    __syncthreads();
    if (t < 2*NK && sh[t]) atomicAdd(&g_hist[t], sh[t]);
}

// ==== segment allocation: warp-aggregated atomic bump; order-free CSR. Also nlive detect. ====
__global__ void __launch_bounds__(256)
k_alloc(){
    int i = blockIdx.x*256 + threadIdx.x;
    int lane = threadIdx.x & 31;
    if (blockIdx.x == 0 && threadIdx.x < 2){
        int base = threadIdx.x*NK, n = 0, kl = 0;
        for (int k = 0; k < NK; k++) if (g_hist[base+k] > 0){ n++; kl = k; }
        g_nlive[threadIdx.x] = n; g_klive[threadIdx.x] = kl;
    }
    int d = (i < Nn) ? g_deg[i] : 0;
    int sc = d;
    #pragma unroll
    for (int off = 1; off < 32; off <<= 1){
        int y = __shfl_up_sync(FULL, sc, off);
        if (lane >= off) sc += y;
    }
    int tot = __shfl_sync(FULL, sc, 31);
    int base = 0;
    if (lane == 31 && tot) base = atomicAdd(&g_total, tot);
    base = __shfl_sync(FULL, base, 31);
    if (i < Nn){
        int my = base + sc - d;
        g_off[i] = my; g_cur[i] = my; g_end[i] = my + d;
        g_deg[i] = 0;
    }
}

// ==== fused: blocks [0,EDGE_BLKS) CSR fill; blocks [EDGE_BLKS,..) PQ layer 0 (general only) ====
__global__ void __launch_bounds__(256)
k_fillPQ(const int* dst, const int* src, const float* attr, const float* xin){
    if (blockIdx.x < EDGE_BLKS){
        bool fastboth = (g_nlive[0] == 1) & (g_nlive[1] == 1);
        int e = blockIdx.x*256 + threadIdx.x;
        if (e < Ee){
            unsigned px = (unsigned)src[e];
            if (!fastboth)
                px |= ((unsigned)g_k0[e] << 16) | ((unsigned)g_k1[e] << 24);
            uint2 pl; pl.x = px; pl.y = __float_as_uint(attr[e]);
            int p = atomicAdd(&g_cur[dst[e]], 1);
            g_ebuf[p] = pl;
        }
        return;
    }
    if (g_nlive[0] == 1) return;     // fast path: PQ not needed
    int lane = threadIdx.x & 31;
    int u = (blockIdx.x - EDGE_BLKS)*8 + (threadIdx.x >> 5);
    if (u >= Nn) return;
    float xv_l = (lane < D0) ? __ldg(xin + (size_t)u*D0 + lane) : 0.f;
    for (int k = 0; k < NK; k++){
        if (g_hist[k] == 0) continue;
        float p = 0.f, q = 0.f;
        for (int i = 0; i < D0; i++){
            float xv = __shfl_sync(FULL, xv_l, i);
            p = fmaf(xv, __ldg(g_A0 + k*D0*Hh + i*Hh + lane), p);
            q = fmaf(xv, __ldg(g_B0 + k*D0*Hh + i*Hh + lane), q);
        }
        size_t ro = ((size_t)(k*Nn + u))*64;
        g_PQ[ro + lane] = p;
        g_PQ[ro + 32 + lane] = q;
    }
}

// ==== PQ layer 1 (general path only; BN+ReLU inline from layer-0 stats) ====
__global__ void __launch_bounds__(256)
k_PQ1(const float* gamma, const float* beta){
    if (g_nlive[1] == 1) return;
    int lane = threadIdx.x & 31;
    int u = blockIdx.x*8 + (threadIdx.x >> 5);
    if (u >= Nn) return;
    float mu  = g_stats[lane]    * (1.f/(float)Nn);
    float var = g_stats[32+lane] * (1.f/(float)Nn) - mu*mu;
    float sc  = rsqrtf(var + EPSI) * __ldg(gamma+lane);
    float shf = __ldg(beta+lane) - mu*sc;
    float xv_l = fmaxf(g_h[(size_t)u*32 + lane]*sc + shf, 0.f);
    for (int k = 0; k < NK; k++){
        if (g_hist[NK + k] == 0) continue;
        float p = 0.f, q = 0.f;
        for (int i = 0; i < Hh; i++){
            float xv = __shfl_sync(FULL, xv_l, i);
            p = fmaf(xv, __ldg(g_A1 + k*Hh*Hh + i*Hh + lane), p);
            q = fmaf(xv, __ldg(g_B1 + k*Hh*Hh + i*Hh + lane), q);
        }
        size_t ro = ((size_t)(k*Nn + u))*64;
        g_PQ[ro + lane] = p;
        g_PQ[ro + 32 + lane] = q;
    }
}

// ==== PERSISTENT aggregation; low-MIO epilogue (reg weights DIN=16, float2 smem DIN=32) ====
template<int DIN, int LAYER>
__global__ void __launch_bounds__(256)
k_agg(const float* __restrict__ xin, const float* __restrict__ root,
      const float* __restrict__ bias, const float* __restrict__ gamma0,
      const float* __restrict__ beta0, float* __restrict__ hout){
    constexpr int NC = DIN/4;        // float4 chunks per x row
    constexpr int NS = 32/NC;        // edge slots per stream
    __shared__ float sR[DIN*32];
    __shared__ float sAB[(DIN==32) ? 32*64 : 2];   // interleaved (A,B) pairs, layer-1 only
    __shared__ float sScale[32], sShift[32], sBias[32];
    __shared__ float sAcc[8][32];
    __shared__ float ss[32], sq[32];
    int t = threadIdx.x, lane = t & 31, w = t >> 5;
    int nlive = g_nlive[LAYER];
    int kl = g_klive[LAYER];
    if (t < 32){ ss[t] = 0.f; sq[t] = 0.f; sBias[t] = __ldg(bias+t); }
    if (LAYER == 1 && t < 32){
        float mu  = g_stats[t]    * (1.f/(float)Nn);
        float var = g_stats[32+t] * (1.f/(float)Nn) - mu*mu;
        float sc  = rsqrtf(var + EPSI) * __ldg(gamma0+t);
        sScale[t] = sc;
        sShift[t] = __ldg(beta0+t) - mu*sc;
    }
    for (int d = t; d < DIN*32; d += 256) sR[d] = __ldg(root + d);
    const float* A = LAYER ? g_A1 : g_A0;
    const float* B = LAYER ? g_B1 : g_B0;
    float rA[(DIN==16)?16:1], rB[(DIN==16)?16:1];
    if (nlive == 1){
        if (DIN == 16){
            #pragma unroll
            for (int i = 0; i < ((DIN==16)?16:1); i++){
                rA[i] = __ldg(A + kl*DIN*32 + i*32 + lane);
                rB[i] = __ldg(B + kl*DIN*32 + i*32 + lane);
            }
        } else {
            for (int d = t; d < 32*32; d += 256){
                float2 v;
                v.x = __ldg(A + kl*1024 + d);
                v.y = __ldg(B + kl*1024 + d);
                *(float2*)&sAB[(d>>5)*64 + (d&31)*2] = v;
            }
        }
    }
    __syncthreads();

    int slot, c;
    if (nlive == 1){ slot = lane / NC; c = lane % NC; }
    else           { slot = lane >> 3; c = lane & 7; }
    const float4* x4 = (const float4*)xin;
    float accS = 0.f, accQ = 0.f;     // per-warp BN-stat accumulators (lane=feature)

    for (int v = blockIdx.x*8 + w; v < Nn; v += gridDim.x*8){
        int s = g_off[v], e1 = g_end[v];
        float msg;
        if (nlive == 1){
            // ---------- fast path: two pipelined streams, 2*NS edges in flight ----------
            float4 ya0={0,0,0,0}, yb0={0,0,0,0}, ya1={0,0,0,0}, yb1={0,0,0,0};
            int i0 = s + slot, i1 = i0 + NS;
            bool v0 = i0 < e1, v1 = i1 < e1;
            uint2 p0, p1;
            if (v0) p0 = g_ebuf[i0];
            if (v1) p1 = g_ebuf[i1];
            while (__any_sync(FULL, v0)){
                int n0 = i0 + 2*NS, n1 = i1 + 2*NS;
                bool w0 = n0 < e1, w1 = n1 < e1;
                uint2 q0, q1;
                if (w0) q0 = g_ebuf[n0];
                if (w1) q1 = g_ebuf[n1];
                if (v0){
                    int u = p0.x & 0xFFFF; float a = __uint_as_float(p0.y);
                    float4 xc = x4[(size_t)u*NC + c];
                    if (LAYER == 1){
                        int f = c*4;
                        xc.x = fmaxf(xc.x*sScale[f+0] + sShift[f+0], 0.f);
                        xc.y = fmaxf(xc.y*sScale[f+1] + sShift[f+1], 0.f);
                        xc.z = fmaxf(xc.z*sScale[f+2] + sShift[f+2], 0.f);
                        xc.w = fmaxf(xc.w*sScale[f+3] + sShift[f+3], 0.f);
                    }
                    ya0.x = fmaf(a, xc.x, ya0.x); yb0.x += xc.x;
                    ya0.y = fmaf(a, xc.y, ya0.y); yb0.y += xc.y;
                    ya0.z = fmaf(a, xc.z, ya0.z); yb0.z += xc.z;
                    ya0.w = fmaf(a, xc.w, ya0.w); yb0.w += xc.w;
                }
                if (v1){
                    int u = p1.x & 0xFFFF; float a = __uint_as_float(p1.y);
                    float4 xc = x4[(size_t)u*NC + c];
                    if (LAYER == 1){
                        int f = c*4;
                        xc.x = fmaxf(xc.x*sScale[f+0] + sShift[f+0], 0.f);
                        xc.y = fmaxf(xc.y*sScale[f+1] + sShift[f+1], 0.f);
                        xc.z = fmaxf(xc.z*sScale[f+2] + sShift[f+2], 0.f);
                        xc.w = fmaxf(xc.w*sScale[f+3] + sShift[f+3], 0.f);
                    }
                    ya1.x = fmaf(a, xc.x, ya1.x); yb1.x += xc.x;
                    ya1.y = fmaf(a, xc.y, ya1.y); yb1.y += xc.y;
                    ya1.z = fmaf(a, xc.z, ya1.z); yb1.z += xc.z;
                    ya1.w = fmaf(a, xc.w, ya1.w); yb1.w += xc.w;
                }
                i0 = n0; i1 = n1; v0 = w0; v1 = w1; p0 = q0; p1 = q1;
            }
            float4 ya, yb;
            ya.x = ya0.x + ya1.x; ya.y = ya0.y + ya1.y;
            ya.z = ya0.z + ya1.z; ya.w = ya0.w + ya1.w;
            yb.x = yb0.x + yb1.x; yb.y = yb0.y + yb1.y;
            yb.z = yb0.z + yb1.z; yb.w = yb0.w + yb1.w;
            #pragma unroll
            for (int off = NC; off < 32; off <<= 1){
                ya.x += __shfl_xor_sync(FULL, ya.x, off);
                ya.y += __shfl_xor_sync(FULL, ya.y, off);
                ya.z += __shfl_xor_sync(FULL, ya.z, off);
                ya.w += __shfl_xor_sync(FULL, ya.w, off);
                yb.x += __shfl_xor_sync(FULL, yb.x, off);
                yb.y += __shfl_xor_sync(FULL, yb.y, off);
                yb.z += __shfl_xor_sync(FULL, yb.z, off);
                yb.w += __shfl_xor_sync(FULL, yb.w, off);
            }
            // epilogue matmul: zero-LDS (DIN=16, reg weights) or 1 LDS.64 per dim (DIN=32)
            msg = 0.f;
            if (DIN == 16){
                #pragma unroll
                for (int i = 0; i < ((DIN==16)?16:1); i++){
                    msg = fmaf(BCAST4(ya, i), rA[i], msg);
                    msg = fmaf(BCAST4(yb, i), rB[i], msg);
                }
            } else {
                #pragma unroll
                for (int i = 0; i < DIN; i++){
                    float2 ab = *(const float2*)&sAB[i*64 + lane*2];
                    msg = fmaf(BCAST4(ya, i), ab.x, msg);
                    msg = fmaf(BCAST4(yb, i), ab.y, msg);
                }
            }
        } else {
            // ---------- general path: gather P/Q rows ----------
            int shift = 16 + (LAYER << 3);
            float4 acc = {0,0,0,0};
            for (int base = s; base < e1; base += 4){
                int i = base + slot;
                if (i < e1){
                    uint2 pl = g_ebuf[i];
                    int u = pl.x & 0xFFFF; int kk = (pl.x >> shift) & 0xFF;
                    float a = __uint_as_float(pl.y);
                    const float4* row = (const float4*)(g_PQ + ((size_t)(kk*Nn + u))*64);
                    float4 p = row[c], q = row[8+c];
                    acc.x = fmaf(a, p.x, acc.x) + q.x;
                    acc.y = fmaf(a, p.y, acc.y) + q.y;
                    acc.z = fmaf(a, p.z, acc.z) + q.z;
                    acc.w = fmaf(a, p.w, acc.w) + q.w;
                }
            }
            #pragma unroll
            for (int off = 8; off < 32; off <<= 1){
                acc.x += __shfl_xor_sync(FULL, acc.x, off);
                acc.y += __shfl_xor_sync(FULL, acc.y, off);
                acc.z += __shfl_xor_sync(FULL, acc.z, off);
                acc.w += __shfl_xor_sync(FULL, acc.w, off);
            }
            if (lane < 8){
                int f = lane*4;
                sAcc[w][f+0] = acc.x; sAcc[w][f+1] = acc.y;
                sAcc[w][f+2] = acc.z; sAcc[w][f+3] = acc.w;
            }
            __syncwarp();
            msg = sAcc[w][lane];
        }

        // ---------- epilogue for this node ----------
        float inv = 1.f / fmaxf((float)(e1 - s), 1.f);
        float xv = 0.f;
        if (lane < DIN){
            xv = __ldg(xin + (size_t)v*DIN + lane);
            if (LAYER == 1) xv = fmaxf(xv*sScale[lane] + sShift[lane], 0.f);
        }
        float rt = 0.f;
        #pragma unroll
        for (int i = 0; i < DIN; i++)
            rt = fmaf(__shfl_sync(FULL, xv, i), sR[i*32+lane], rt);
        float o = rt + msg*inv + sBias[lane];
        hout[(size_t)v*32 + lane] = o;
        accS += o;
        accQ = fmaf(o, o, accQ);
    }
    // flush per-warp stats: 8 smem atomics per feature per block, then 1 global per block
    atomicAdd(&ss[lane], accS);
    atomicAdd(&sq[lane], accQ);
    __syncthreads();
    if (t < 32){
        atomicAdd(&g_stats[LAYER*64 + t],      ss[t]);
        atomicAdd(&g_stats[LAYER*64 + 32 + t], sq[t]);
    }
}

// ==== BN2 + ReLU + pooling (layer-1 stats) ====
__global__ void __launch_bounds__(256)
k_apply1(const float* h2, const float* gamma, const float* beta, const int* batch){
    int idx = blockIdx.x*blockDim.x + threadIdx.x;
    if (idx >= Nn*Hh) return;
    int f = idx & 31, v = idx >> 5;
    float mu  = g_stats[64+f] * (1.f/(float)Nn);
    float var = g_stats[96+f] * (1.f/(float)Nn) - mu*mu;
    float sc  = rsqrtf(var + EPSI) * __ldg(gamma+f);
    float xv = fmaxf((h2[idx] - mu)*sc + __ldg(beta+f), 0.f);
    int g = batch[v];
    atomicAdd(&g_pool[g*Hh + f], xv);
    if (f == 0) atomicAdd(&g_pcnt[g], 1);
}

// ==== readout MLP; self-cleans g_hist + g_total ====
__global__ void __launch_bounds__(64)
k_mlp(const float* edft, const float* w1, const float* b1,
      const float* w2, const float* b2, float* out){
    int g = threadIdx.x;
    g_hist[g] = 0;
    if (g < 2*NK - 64) g_hist[64 + g] = 0;
    if (g == 0) g_total = 0;
    if (g >= Gg) return;
    float zin[Hh+1];
    float inv = 1.f / fmaxf((float)g_pcnt[g], 1.f);
    for (int i = 0; i < Hh; i++) zin[i] = g_pool[g*Hh+i]*inv;
    zin[Hh] = edft[g];
    float o = b2[0];
    for (int j = 0; j < 64; j++){
        float hsum = b1[j];
        #pragma unroll
        for (int i = 0; i < Hh+1; i++) hsum = fmaf(zin[i], w1[i*64+j], hsum);
        o = fmaf(fmaxf(hsum, 0.f), w2[j], o);
    }
    out[g] = o;
}

extern "C" void kernel_launch(void* const* d_in, const int* in_sizes, int n_in,
                              void* d_out, int out_size){
    const float* x     = (const float*)d_in[0];
    const float* attr  = (const float*)d_in[1];
    const float* edft  = (const float*)d_in[2];
    const int*   src   = (const int*)  d_in[3];
    const int*   dst   = (const int*)  d_in[4];
    const int*   batch = (const int*)  d_in[5];
    const float* l0w1=(const float*)d_in[6],  *l0b1=(const float*)d_in[7];
    const float* l0w2=(const float*)d_in[8],  *l0b2=(const float*)d_in[9];
    const float* l0root=(const float*)d_in[10],*l0bias=(const float*)d_in[11];
    const float* l0g=(const float*)d_in[12],  *l0be=(const float*)d_in[13];
    const float* l1w1=(const float*)d_in[14], *l1b1=(const float*)d_in[15];
    const float* l1w2=(const float*)d_in[16], *l1b2=(const float*)d_in[17];
    const float* l1root=(const float*)d_in[18],*l1bias=(const float*)d_in[19];
    const float* l1g=(const float*)d_in[20],  *l1be=(const float*)d_in[21];
    const float* mw1=(const float*)d_in[22],  *mb1=(const float*)d_in[23];
    const float* mw2=(const float*)d_in[24],  *mb2=(const float*)d_in[25];
    float* out = (float*)d_out;

    void *pH, *pHn;
    cudaGetSymbolAddress(&pH,  g_h);
    cudaGetSymbolAddress(&pHn, g_hn);
    float* h  = (float*)pH;
    float* h2 = (float*)pHn;

    k_pre<<<2*NK + EDGE_BLKS, 256>>>(attr, dst,
                                     l0w1,l0b1,l0w2,l0b2, l1w1,l1b1,l1w2,l1b2);
    k_alloc<<<(Nn+255)/256,256>>>();
    k_fillPQ<<<EDGE_BLKS + AGG_BLKS, 256>>>(dst, src, attr, x);

    k_agg<D0,0><<<444,256>>>(x, l0root, l0bias, l0g, l0be, h);   // 3 blocks/SM resident
    k_PQ1<<<AGG_BLKS,256>>>(l0g, l0be);
    k_agg<Hh,1><<<592,256>>>(h, l1root, l1bias, l0g, l0be, h2);  // 4 blocks/SM resident
    k_apply1<<<(Nn*Hh+255)/256,256>>>(h2, l1g, l1be, batch);
    k_mlp<<<1,64>>>(edft, mw1, mb1, mw2, mb2, out);
}

// round 11
// speedup vs baseline: 1.0638x; 1.0638x over previous
#include <cuda_runtime.h>
#include <cfloat>

#define Nn 20000
#define Ee 320000
#define Gg 64
#define D0 16
#define Hh 32
#define NK 33
#define EPSI 1e-5f
#define FULL 0xffffffffu
#define EDGE_BLKS 1250        /* ceil(Ee/256) */
#define ALLOC_UNITS 79        /* ceil(Nn/256) */

// ---------------- static device scratch (zero-init at load; self-cleaning across replays) ----------------
__device__ float g_A0[NK*D0*Hh], g_B0[NK*D0*Hh];
__device__ float g_A1[NK*Hh*Hh], g_B1[NK*Hh*Hh];
__device__ unsigned char g_k0[Ee], g_k1[Ee];
__device__ int g_hist[2*NK];            // zeroed in final phase each run
__device__ int g_deg[Nn];               // zeroed in alloc phase after read
__device__ int g_total;                 // zeroed in final phase each run
__device__ int g_off[Nn], g_end[Nn], g_cur[Nn];
__device__ int g_nlive[2], g_klive[2];
__device__ uint2 g_ebuf[Ee];
__device__ __align__(16) float g_PQ[(size_t)NK*Nn*64];   // general path only
__device__ __align__(16) float g_h[Nn*Hh], g_hn[Nn*Hh];
__device__ float g_stats[4*Hh];         // [sum0|sq0|sum1|sq1]
__device__ float g_pool[Gg*Hh];
__device__ int   g_pcnt[Gg];
// sense-reversing grid barriers: counters reset by releaser, senses toggle (replay-safe)
__device__ int g_bcnt[8];
__device__ volatile int g_bsense[8];

__device__ __forceinline__ void gridbar(int i){
    __syncthreads();
    if (threadIdx.x == 0){
        int sense = g_bsense[i];
        __threadfence();
        if (atomicAdd(&g_bcnt[i], 1) == (int)gridDim.x - 1){
            g_bcnt[i] = 0;
            __threadfence();
            g_bsense[i] = sense ^ 1;
        } else {
            while (g_bsense[i] == sense) __nanosleep(64);
            __threadfence();
        }
    }
    __syncthreads();
}

__device__ __forceinline__ void rank32(float wj, float bj, float& t, int& r, int j){
    t = (wj != 0.0f) ? (-bj / wj) : FLT_MAX;
    r = 0;
    #pragma unroll
    for (int m = 0; m < 32; m++){
        float tm = __shfl_sync(FULL, t, m);
        r += (tm < t || (tm == t && m < j));
    }
}

// ==== persistent aggregation phase (R8-proven form); per-warp stat regs, smem flush ====
template<int DIN, int LAYER>
__device__ __forceinline__ void agg_phase(
    const float* __restrict__ xin, const float* __restrict__ root,
    const float* __restrict__ bias, const float* __restrict__ gamma0,
    const float* __restrict__ beta0, float* __restrict__ hout,
    float* sA, float* sB, float* sR, float* sSc, float* sSh, float* sBi,
    float* ssum, float* ssq, float (*sAcc)[64], int nlive, int kl)
{
    constexpr int NC = DIN/4;        // float4 chunks per x row
    constexpr int NS = 32/NC;        // edge slots per stream
    int t = threadIdx.x, lane = t & 31, w = t >> 5;
    __syncthreads();
    if (t < 32){
        ssum[t] = 0.f; ssq[t] = 0.f; sBi[t] = __ldg(bias + t);
        if (LAYER == 1){
            float mu  = __ldcg(&g_stats[t])    * (1.f/(float)Nn);
            float var = __ldcg(&g_stats[32+t]) * (1.f/(float)Nn) - mu*mu;
            float sc  = rsqrtf(var + EPSI) * __ldg(gamma0 + t);
            sSc[t] = sc;
            sSh[t] = __ldg(beta0 + t) - mu*sc;
        }
    }
    for (int d = t; d < DIN*32; d += 256) sR[d] = __ldg(root + d);
    if (nlive == 1){
        const float* A = LAYER ? g_A1 : g_A0;
        const float* B = LAYER ? g_B1 : g_B0;
        for (int d = t; d < DIN*32; d += 256){
            sA[d] = A[kl*DIN*32 + d];       // written earlier this kernel: plain loads
            sB[d] = B[kl*DIN*32 + d];
        }
    }
    __syncthreads();

    int slot, c;
    if (nlive == 1){ slot = lane / NC; c = lane % NC; }
    else           { slot = lane >> 3; c = lane & 7; }
    const float4* x4 = (const float4*)xin;
    float accS = 0.f, accQ = 0.f;

    for (int v = blockIdx.x*8 + w; v < Nn; v += gridDim.x*8){
        int s = g_off[v], e1 = g_end[v];
        float msg;
        if (nlive == 1){
            float4 ya0={0,0,0,0}, yb0={0,0,0,0}, ya1={0,0,0,0}, yb1={0,0,0,0};
            int i0 = s + slot, i1 = i0 + NS;
            bool v0 = i0 < e1, v1 = i1 < e1;
            uint2 p0 = make_uint2(0,0), p1 = make_uint2(0,0);
            if (v0) p0 = __ldcg(&g_ebuf[i0]);
            if (v1) p1 = __ldcg(&g_ebuf[i1]);
            while (__any_sync(FULL, v0)){
                int n0 = i0 + 2*NS, n1 = i1 + 2*NS;
                bool w0 = n0 < e1, w1 = n1 < e1;
                uint2 q0 = make_uint2(0,0), q1 = make_uint2(0,0);
                if (w0) q0 = __ldcg(&g_ebuf[n0]);
                if (w1) q1 = __ldcg(&g_ebuf[n1]);
                if (v0){
                    int u = p0.x & 0xFFFF; float a = __uint_as_float(p0.y);
                    float4 xc = x4[(size_t)u*NC + c];
                    if (LAYER == 1){
                        int f = c*4;
                        xc.x = fmaxf(xc.x*sSc[f+0] + sSh[f+0], 0.f);
                        xc.y = fmaxf(xc.y*sSc[f+1] + sSh[f+1], 0.f);
                        xc.z = fmaxf(xc.z*sSc[f+2] + sSh[f+2], 0.f);
                        xc.w = fmaxf(xc.w*sSc[f+3] + sSh[f+3], 0.f);
                    }
                    ya0.x = fmaf(a, xc.x, ya0.x); yb0.x += xc.x;
                    ya0.y = fmaf(a, xc.y, ya0.y); yb0.y += xc.y;
                    ya0.z = fmaf(a, xc.z, ya0.z); yb0.z += xc.z;
                    ya0.w = fmaf(a, xc.w, ya0.w); yb0.w += xc.w;
                }
                if (v1){
                    int u = p1.x & 0xFFFF; float a = __uint_as_float(p1.y);
                    float4 xc = x4[(size_t)u*NC + c];
                    if (LAYER == 1){
                        int f = c*4;
                        xc.x = fmaxf(xc.x*sSc[f+0] + sSh[f+0], 0.f);
                        xc.y = fmaxf(xc.y*sSc[f+1] + sSh[f+1], 0.f);
                        xc.z = fmaxf(xc.z*sSc[f+2] + sSh[f+2], 0.f);
                        xc.w = fmaxf(xc.w*sSc[f+3] + sSh[f+3], 0.f);
                    }
                    ya1.x = fmaf(a, xc.x, ya1.x); yb1.x += xc.x;
                    ya1.y = fmaf(a, xc.y, ya1.y); yb1.y += xc.y;
                    ya1.z = fmaf(a, xc.z, ya1.z); yb1.z += xc.z;
                    ya1.w = fmaf(a, xc.w, ya1.w); yb1.w += xc.w;
                }
                i0 = n0; i1 = n1; v0 = w0; v1 = w1; p0 = q0; p1 = q1;
            }
            float4 ya, yb;
            ya.x = ya0.x + ya1.x; ya.y = ya0.y + ya1.y;
            ya.z = ya0.z + ya1.z; ya.w = ya0.w + ya1.w;
            yb.x = yb0.x + yb1.x; yb.y = yb0.y + yb1.y;
            yb.z = yb0.z + yb1.z; yb.w = yb0.w + yb1.w;
            #pragma unroll
            for (int off = NC; off < 32; off <<= 1){
                ya.x += __shfl_xor_sync(FULL, ya.x, off);
                ya.y += __shfl_xor_sync(FULL, ya.y, off);
                ya.z += __shfl_xor_sync(FULL, ya.z, off);
                ya.w += __shfl_xor_sync(FULL, ya.w, off);
                yb.x += __shfl_xor_sync(FULL, yb.x, off);
                yb.y += __shfl_xor_sync(FULL, yb.y, off);
                yb.z += __shfl_xor_sync(FULL, yb.z, off);
                yb.w += __shfl_xor_sync(FULL, yb.w, off);
            }
            if (lane < NC){
                int f = lane*4;
                sAcc[w][f+0] = ya.x; sAcc[w][f+1] = ya.y;
                sAcc[w][f+2] = ya.z; sAcc[w][f+3] = ya.w;
                sAcc[w][DIN+f+0] = yb.x; sAcc[w][DIN+f+1] = yb.y;
                sAcc[w][DIN+f+2] = yb.z; sAcc[w][DIN+f+3] = yb.w;
            }
            __syncwarp();
            msg = 0.f;
            #pragma unroll
            for (int i = 0; i < DIN; i++){
                msg = fmaf(sAcc[w][i],     sA[i*32+lane], msg);
                msg = fmaf(sAcc[w][DIN+i], sB[i*32+lane], msg);
            }
        } else {
            int shift = 16 + (LAYER << 3);
            float4 acc = {0,0,0,0};
            for (int base = s; base < e1; base += 4){
                int i = base + slot;
                if (i < e1){
                    uint2 pl = __ldcg(&g_ebuf[i]);
                    int u = pl.x & 0xFFFF; int kk = (pl.x >> shift) & 0xFF;
                    float a = __uint_as_float(pl.y);
                    const float4* row = (const float4*)(g_PQ + ((size_t)(kk*Nn + u))*64);
                    float4 p = row[c], q = row[8+c];
                    acc.x = fmaf(a, p.x, acc.x) + q.x;
                    acc.y = fmaf(a, p.y, acc.y) + q.y;
                    acc.z = fmaf(a, p.z, acc.z) + q.z;
                    acc.w = fmaf(a, p.w, acc.w) + q.w;
                }
            }
            #pragma unroll
            for (int off = 8; off < 32; off <<= 1){
                acc.x += __shfl_xor_sync(FULL, acc.x, off);
                acc.y += __shfl_xor_sync(FULL, acc.y, off);
                acc.z += __shfl_xor_sync(FULL, acc.z, off);
                acc.w += __shfl_xor_sync(FULL, acc.w, off);
            }
            if (lane < 8){
                int f = lane*4;
                sAcc[w][f+0] = acc.x; sAcc[w][f+1] = acc.y;
                sAcc[w][f+2] = acc.z; sAcc[w][f+3] = acc.w;
            }
            __syncwarp();
            msg = sAcc[w][lane];
        }

        float inv = 1.f / fmaxf((float)(e1 - s), 1.f);
        float xv = 0.f;
        if (lane < DIN){
            xv = xin[(size_t)v*DIN + lane];     // may be g_h (written this kernel): plain load
            if (LAYER == 1) xv = fmaxf(xv*sSc[lane] + sSh[lane], 0.f);
        }
        float rt = 0.f;
        #pragma unroll
        for (int i = 0; i < DIN; i++)
            rt = fmaf(__shfl_sync(FULL, xv, i), sR[i*32+lane], rt);
        float o = rt + msg*inv + sBi[lane];
        hout[(size_t)v*32 + lane] = o;
        accS += o;
        accQ = fmaf(o, o, accQ);
    }
    atomicAdd(&ssum[lane], accS);
    atomicAdd(&ssq[lane], accQ);
    __syncthreads();
    if (t < 32){
        atomicAdd(&g_stats[LAYER*64 + t],      ssum[t]);
        atomicAdd(&g_stats[LAYER*64 + 32 + t], ssq[t]);
    }
}

// ==== single persistent mega-kernel: all phases, software grid barriers ====
__global__ void __launch_bounds__(256, 4)
k_mega(const float* __restrict__ x, const float* __restrict__ attr,
       const float* __restrict__ edft, const int* __restrict__ src,
       const int* __restrict__ dst, const int* __restrict__ batch,
       const float* l0w1, const float* l0b1, const float* l0w2, const float* l0b2,
       const float* l0root, const float* l0bias, const float* l0g, const float* l0be,
       const float* l1w1, const float* l1b1, const float* l1w2, const float* l1b2,
       const float* l1root, const float* l1bias, const float* l1g, const float* l1be,
       const float* mw1, const float* mb1, const float* mw2, const float* mb2,
       float* out)
{
    __shared__ float sW0[1024], sW1[1024], sW2[1024];      // 12 KB phase-union
    __shared__ float sSc[32], sSh[32], sBi[32], ssum[32], ssq[32];
    __shared__ float sAcc[8][64];
    int t = threadIdx.x, lane = t & 31;

    // -------- P0: zero accumulators (block 0) + buildAB + edge classify/hist/deg --------
    if (blockIdx.x == 0){
        for (int i = t; i < 4*Hh; i += 256) g_stats[i] = 0.f;
        for (int i = t; i < Gg*Hh; i += 256) g_pool[i] = 0.f;
        if (t < Gg) g_pcnt[t] = 0;
    }
    for (int unit = blockIdx.x; unit < 2*NK + EDGE_BLKS; unit += gridDim.x){
        __syncthreads();
        if (unit < 2*NK){
            int layer = (unit >= NK);
            int k = unit - layer*NK;
            int D = layer ? (Hh*Hh) : (D0*Hh);
            float* A = layer ? g_A1 : g_A0;
            float* B = layer ? g_B1 : g_B0;
            const float* ew1 = layer ? l1w1 : l0w1;
            const float* eb1 = layer ? l1b1 : l0b1;
            const float* ew2 = layer ? l1w2 : l0w2;
            const float* eb2 = layer ? l1b2 : l0b2;
            float* sw = sW0; float* sb = sW0 + 32; int* sr = (int*)sW1;
            if (t < 32){
                float wj = ew1[t], bj = eb1[t], tv; int r;
                rank32(wj, bj, tv, r, t);
                sw[t] = wj; sb[t] = bj; sr[t] = r;
            }
            __syncthreads();
            for (int d = t; d < D; d += 256){
                float a = 0.f, b = eb2[d];
                for (int j = 0; j < 32; j++){
                    float wj = sw[j];
                    bool act = (wj > 0.f) ? (k > sr[j]) : ((wj < 0.f) ? (k <= sr[j]) : (sb[j] > 0.f));
                    if (act){ float w2 = ew2[j*D+d]; a += wj*w2; b += sb[j]*w2; }
                }
                A[k*D+d] = a; B[k*D+d] = b;
            }
        } else {
            float* st0 = sW0; float* st1 = sW0 + 32; int* sh = (int*)sW1;
            if (t < 32){ float tv; int r; rank32(l0w1[t], l0b1[t], tv, r, t); st0[r] = tv; }
            else if (t < 64){ int j = t-32; float tv; int r; rank32(l1w1[j], l1b1[j], tv, r, j); st1[r] = tv; }
            if (t < 2*NK) sh[t] = 0;
            __syncthreads();
            int e = (unit - 2*NK)*256 + t;
            bool valid = (e < Ee);
            float a = valid ? attr[e] : -FLT_MAX;
            int k0 = 0, k1 = 0;
            #pragma unroll
            for (int step = 16; step > 0; step >>= 1){
                if (st0[k0 + step - 1] <= a) k0 += step;
                if (st1[k1 + step - 1] <= a) k1 += step;
            }
            k0 += (st0[k0] <= a);   // counts range [0,32]
            k1 += (st1[k1] <= a);
            if (valid){
                g_k0[e] = (unsigned char)k0; g_k1[e] = (unsigned char)k1;
                atomicAdd(&g_deg[dst[e]], 1);
            }
            int key0 = valid ? k0 : -1;
            unsigned m0 = __match_any_sync(FULL, key0);
            if (valid && lane == (__ffs(m0)-1)) atomicAdd(&sh[k0], __popc(m0));
            int key1 = valid ? k1 : -1;
            unsigned m1 = __match_any_sync(FULL, key1);
            if (valid && lane == (__ffs(m1)-1)) atomicAdd(&sh[NK+k1], __popc(m1));
            __syncthreads();
            if (t < 2*NK && sh[t]) atomicAdd(&g_hist[t], sh[t]);
        }
    }
    gridbar(0);

    // -------- P1: segment allocation + live-interval detect --------
    for (int unit = blockIdx.x; unit < ALLOC_UNITS; unit += gridDim.x){
        int i = unit*256 + t;
        int d = (i < Nn) ? g_deg[i] : 0;
        int sc = d;
        #pragma unroll
        for (int off = 1; off < 32; off <<= 1){
            int y = __shfl_up_sync(FULL, sc, off);
            if (lane >= off) sc += y;
        }
        int tot = __shfl_sync(FULL, sc, 31);
        int base = 0;
        if (lane == 31 && tot) base = atomicAdd(&g_total, tot);
        base = __shfl_sync(FULL, base, 31);
        if (i < Nn){
            int my = base + sc - d;
            g_off[i] = my; g_cur[i] = my; g_end[i] = my + d;
            g_deg[i] = 0;
        }
    }
    if (blockIdx.x == 0 && t < 2){
        int bb = t*NK, n = 0, kl = 0;
        for (int k = 0; k < NK; k++) if (g_hist[bb+k] > 0){ n++; kl = k; }
        g_nlive[t] = n; g_klive[t] = kl;
    }
    gridbar(1);

    int nl0 = g_nlive[0], kl0 = g_klive[0];
    int nl1 = g_nlive[1], kl1 = g_klive[1];
    bool fastboth = (nl0 == 1) && (nl1 == 1);

    // -------- P2: CSR fill (+ PQ layer 0 when general path) --------
    for (int unit = blockIdx.x; unit < EDGE_BLKS; unit += gridDim.x){
        int e = unit*256 + t;
        if (e < Ee){
            unsigned px = (unsigned)src[e];
            if (!fastboth) px |= ((unsigned)g_k0[e] << 16) | ((unsigned)g_k1[e] << 24);
            uint2 pl; pl.x = px; pl.y = __float_as_uint(attr[e]);
            int p = atomicAdd(&g_cur[dst[e]], 1);
            g_ebuf[p] = pl;
        }
    }
    if (nl0 > 1){
        int w = t >> 5;
        for (int u = blockIdx.x*8 + w; u < Nn; u += gridDim.x*8){
            float xv_l = (lane < D0) ? __ldg(x + (size_t)u*D0 + lane) : 0.f;
            for (int k = 0; k < NK; k++){
                if (g_hist[k] == 0) continue;
                float p = 0.f, q = 0.f;
                for (int i = 0; i < D0; i++){
                    float xv = __shfl_sync(FULL, xv_l, i);
                    p = fmaf(xv, g_A0[k*D0*Hh + i*Hh + lane], p);
                    q = fmaf(xv, g_B0[k*D0*Hh + i*Hh + lane], q);
                }
                size_t ro = ((size_t)(k*Nn + u))*64;
                g_PQ[ro + lane] = p;
                g_PQ[ro + 32 + lane] = q;
            }
        }
    }
    gridbar(2);

    // -------- P3: aggregation layer 0 --------
    agg_phase<D0,0>(x, l0root, l0bias, l0g, l0be, g_h,
                    sW0, sW1, sW2, sSc, sSh, sBi, ssum, ssq, sAcc, nl0, kl0);
    gridbar(3);

    // -------- P4a: PQ layer 1 (general path only; always barrier) --------
    if (nl1 > 1){
        int w = t >> 5;
        float mu  = __ldcg(&g_stats[lane])    * (1.f/(float)Nn);
        float var = __ldcg(&g_stats[32+lane]) * (1.f/(float)Nn) - mu*mu;
        float sc  = rsqrtf(var + EPSI) * __ldg(l0g + lane);
        float shf = __ldg(l0be + lane) - mu*sc;
        for (int u = blockIdx.x*8 + w; u < Nn; u += gridDim.x*8){
            float xv_l = fmaxf(g_h[(size_t)u*32 + lane]*sc + shf, 0.f);
            for (int k = 0; k < NK; k++){
                if (g_hist[NK + k] == 0) continue;
                float p = 0.f, q = 0.f;
                for (int i = 0; i < Hh; i++){
                    float xv = __shfl_sync(FULL, xv_l, i);
                    p = fmaf(xv, g_A1[k*Hh*Hh + i*Hh + lane], p);
                    q = fmaf(xv, g_B1[k*Hh*Hh + i*Hh + lane], q);
                }
                size_t ro = ((size_t)(k*Nn + u))*64;
                g_PQ[ro + lane] = p;
                g_PQ[ro + 32 + lane] = q;
            }
        }
    }
    gridbar(4);

    // -------- P4: aggregation layer 1 --------
    agg_phase<Hh,1>(g_h, l1root, l1bias, l0g, l0be, g_hn,
                    sW0, sW1, sW2, sSc, sSh, sBi, ssum, ssq, sAcc, nl1, kl1);
    gridbar(5);

    // -------- P5: BN2 + ReLU + pool --------
    __syncthreads();
    if (t < 32){
        float mu  = __ldcg(&g_stats[64+t]) * (1.f/(float)Nn);
        float var = __ldcg(&g_stats[96+t]) * (1.f/(float)Nn) - mu*mu;
        float sc  = rsqrtf(var + EPSI) * __ldg(l1g + t);
        sSc[t] = sc;
        sSh[t] = __ldg(l1be + t) - mu*sc;
    }
    __syncthreads();
    for (int idx = blockIdx.x*256 + t; idx < Nn*Hh; idx += gridDim.x*256){
        int f = idx & 31, v = idx >> 5;
        float xv = fmaxf(g_hn[idx]*sSc[f] + sSh[f], 0.f);
        int g = batch[v];
        atomicAdd(&g_pool[g*Hh + f], xv);
        if (f == 0) atomicAdd(&g_pcnt[g], 1);
    }
    gridbar(6);

    // -------- P6: readout MLP + cleanup (block 0) --------
    if (blockIdx.x == 0){
        if (t < 2*NK) g_hist[t] = 0;
        if (t == 255) g_total = 0;
        if (t < Gg){
            float zin[Hh+1];
            float inv = 1.f / fmaxf((float)__ldcg(&g_pcnt[t]), 1.f);
            for (int i = 0; i < Hh; i++) zin[i] = __ldcg(&g_pool[t*Hh+i])*inv;
            zin[Hh] = edft[t];
            float o = mb2[0];
            for (int j = 0; j < 64; j++){
                float hsum = mb1[j];
                #pragma unroll
                for (int i = 0; i < Hh+1; i++) hsum = fmaf(zin[i], mw1[i*64+j], hsum);
                o = fmaf(fmaxf(hsum, 0.f), mw2[j], o);
            }
            out[t] = o;
        }
    }
}

extern "C" void kernel_launch(void* const* d_in, const int* in_sizes, int n_in,
                              void* d_out, int out_size){
    const float* x     = (const float*)d_in[0];
    const float* attr  = (const float*)d_in[1];
    const float* edft  = (const float*)d_in[2];
    const int*   src   = (const int*)  d_in[3];
    const int*   dst   = (const int*)  d_in[4];
    const int*   batch = (const int*)  d_in[5];
    const float* l0w1=(const float*)d_in[6],  *l0b1=(const float*)d_in[7];
    const float* l0w2=(const float*)d_in[8],  *l0b2=(const float*)d_in[9];
    const float* l0root=(const float*)d_in[10],*l0bias=(const float*)d_in[11];
    const float* l0g=(const float*)d_in[12],  *l0be=(const float*)d_in[13];
    const float* l1w1=(const float*)d_in[14], *l1b1=(const float*)d_in[15];
    const float* l1w2=(const float*)d_in[16], *l1b2=(const float*)d_in[17];
    const float* l1root=(const float*)d_in[18],*l1bias=(const float*)d_in[19];
    const float* l1g=(const float*)d_in[20],  *l1be=(const float*)d_in[21];
    const float* mw1=(const float*)d_in[22],  *mb1=(const float*)d_in[23];
    const float* mw2=(const float*)d_in[24],  *mb2=(const float*)d_in[25];
    float* out = (float*)d_out;

    int dev = 0;
    cudaGetDevice(&dev);
    int nsm = 0;
    cudaDeviceGetAttribute(&nsm, cudaDevAttrMultiProcessorCount, dev);
    if (nsm <= 0) nsm = 148;
    int nb = 0;
    cudaOccupancyMaxActiveBlocksPerMultiprocessor(&nb, k_mega, 256, 0);
    if (nb < 1) nb = 1;
    int grid = nsm * nb;      // every block co-resident: software grid barrier is safe

    k_mega<<<grid, 256>>>(x, attr, edft, src, dst, batch,
                          l0w1, l0b1, l0w2, l0b2, l0root, l0bias, l0g, l0be,
                          l1w1, l1b1, l1w2, l1b2, l1root, l1bias, l1g, l1be,
                          mw1, mb1, mw2, mb2, out);
}

// round 12
// speedup vs baseline: 1.0952x; 1.0295x over previous
#include <cuda_runtime.h>
#include <cfloat>

#define Nn 20000
#define Ee 320000
#define Gg 64
#define D0 16
#define Hh 32
#define NK 33
#define EPSI 1e-5f
#define FULL 0xffffffffu
#define EDGE_BLKS 1250        /* ceil(Ee/256) */
#define ALLOC_UNITS 79        /* ceil(Nn/256) */

// ---------------- static device scratch (zero-init at load; self-cleaning across replays) ----------------
__device__ float g_A0[NK*D0*Hh], g_B0[NK*D0*Hh];
__device__ float g_A1[NK*Hh*Hh], g_B1[NK*Hh*Hh];
__device__ int g_hist[2*NK];            // zeroed in final phase each run
__device__ int g_deg[Nn];               // zeroed in alloc phase after read
__device__ int g_total;                 // zeroed in final phase each run
__device__ int g_off[Nn], g_end[Nn], g_cur[Nn];
__device__ int g_nlive[2], g_klive[2];
__device__ uint2 g_ebuf[Ee];
__device__ __align__(16) float g_PQ[(size_t)NK*Nn*64];   // general path only
__device__ __align__(16) float g_h[Nn*Hh], g_hn[Nn*Hh];
__device__ float g_stats[4*Hh];         // [sum0|sq0|sum1|sq1]
__device__ float g_pool[Gg*Hh];
__device__ int   g_pcnt[Gg];
// sense-reversing grid barriers (replay-safe: counter reset by releaser, sense toggles)
__device__ int g_bcnt[8];
__device__ volatile int g_bsense[8];

__device__ __forceinline__ void gridbar(int i){
    __syncthreads();
    if (threadIdx.x == 0){
        int sense = g_bsense[i];
        __threadfence();
        if (atomicAdd(&g_bcnt[i], 1) == (int)gridDim.x - 1){
            g_bcnt[i] = 0;
            __threadfence();
            g_bsense[i] = sense ^ 1;
        } else {
            while (g_bsense[i] == sense) __nanosleep(64);
            __threadfence();
        }
    }
    __syncthreads();
}

__device__ __forceinline__ void rank32(float wj, float bj, float& t, int& r, int j){
    t = (wj != 0.0f) ? (-bj / wj) : FLT_MAX;
    r = 0;
    #pragma unroll
    for (int m = 0; m < 32; m++){
        float tm = __shfl_sync(FULL, t, m);
        r += (tm < t || (tm == t && m < j));
    }
}

// ==== aggregation phase (no BN inside — inputs are pre-normalized); per-warp stat regs ====
template<int DIN, int LAYER>
__device__ __forceinline__ void agg_phase(
    const float* __restrict__ xin, const float* __restrict__ root,
    const float* __restrict__ bias, float* __restrict__ hout,
    float* sA, float* sB, float* sR, float* sBi,
    float* ssum, float* ssq, float (*sAcc)[64], int nlive, int kl)
{
    constexpr int NC = DIN/4;
    constexpr int NS = 32/NC;
    int t = threadIdx.x, lane = t & 31, w = t >> 5;
    __syncthreads();
    if (t < 32){ ssum[t] = 0.f; ssq[t] = 0.f; sBi[t] = __ldg(bias + t); }
    for (int d = t; d < DIN*32; d += 256) sR[d] = __ldg(root + d);
    if (nlive == 1){
        const float* A = LAYER ? g_A1 : g_A0;
        const float* B = LAYER ? g_B1 : g_B0;
        for (int d = t; d < DIN*32; d += 256){
            sA[d] = A[kl*DIN*32 + d];
            sB[d] = B[kl*DIN*32 + d];
        }
    }
    __syncthreads();

    int slot, c;
    if (nlive == 1){ slot = lane / NC; c = lane % NC; }
    else           { slot = lane >> 3; c = lane & 7; }
    const float4* x4 = (const float4*)xin;
    float accS = 0.f, accQ = 0.f;

    for (int v = blockIdx.x*8 + w; v < Nn; v += gridDim.x*8){
        int s = g_off[v], e1 = g_end[v];
        float msg;
        if (nlive == 1){
            float4 ya0={0,0,0,0}, yb0={0,0,0,0}, ya1={0,0,0,0}, yb1={0,0,0,0};
            int i0 = s + slot, i1 = i0 + NS;
            bool v0 = i0 < e1, v1 = i1 < e1;
            uint2 p0 = make_uint2(0,0), p1 = make_uint2(0,0);
            if (v0) p0 = __ldcg(&g_ebuf[i0]);
            if (v1) p1 = __ldcg(&g_ebuf[i1]);
            while (__any_sync(FULL, v0)){
                int n0 = i0 + 2*NS, n1 = i1 + 2*NS;
                bool w0 = n0 < e1, w1 = n1 < e1;
                uint2 q0 = make_uint2(0,0), q1 = make_uint2(0,0);
                if (w0) q0 = __ldcg(&g_ebuf[n0]);
                if (w1) q1 = __ldcg(&g_ebuf[n1]);
                if (v0){
                    int u = p0.x & 0xFFFF; float a = __uint_as_float(p0.y);
                    float4 xc = x4[(size_t)u*NC + c];
                    ya0.x = fmaf(a, xc.x, ya0.x); yb0.x += xc.x;
                    ya0.y = fmaf(a, xc.y, ya0.y); yb0.y += xc.y;
                    ya0.z = fmaf(a, xc.z, ya0.z); yb0.z += xc.z;
                    ya0.w = fmaf(a, xc.w, ya0.w); yb0.w += xc.w;
                }
                if (v1){
                    int u = p1.x & 0xFFFF; float a = __uint_as_float(p1.y);
                    float4 xc = x4[(size_t)u*NC + c];
                    ya1.x = fmaf(a, xc.x, ya1.x); yb1.x += xc.x;
                    ya1.y = fmaf(a, xc.y, ya1.y); yb1.y += xc.y;
                    ya1.z = fmaf(a, xc.z, ya1.z); yb1.z += xc.z;
                    ya1.w = fmaf(a, xc.w, ya1.w); yb1.w += xc.w;
                }
                i0 = n0; i1 = n1; v0 = w0; v1 = w1; p0 = q0; p1 = q1;
            }
            float4 ya, yb;
            ya.x = ya0.x + ya1.x; ya.y = ya0.y + ya1.y;
            ya.z = ya0.z + ya1.z; ya.w = ya0.w + ya1.w;
            yb.x = yb0.x + yb1.x; yb.y = yb0.y + yb1.y;
            yb.z = yb0.z + yb1.z; yb.w = yb0.w + yb1.w;
            #pragma unroll
            for (int off = NC; off < 32; off <<= 1){
                ya.x += __shfl_xor_sync(FULL, ya.x, off);
                ya.y += __shfl_xor_sync(FULL, ya.y, off);
                ya.z += __shfl_xor_sync(FULL, ya.z, off);
                ya.w += __shfl_xor_sync(FULL, ya.w, off);
                yb.x += __shfl_xor_sync(FULL, yb.x, off);
                yb.y += __shfl_xor_sync(FULL, yb.y, off);
                yb.z += __shfl_xor_sync(FULL, yb.z, off);
                yb.w += __shfl_xor_sync(FULL, yb.w, off);
            }
            if (lane < NC){
                int f = lane*4;
                sAcc[w][f+0] = ya.x; sAcc[w][f+1] = ya.y;
                sAcc[w][f+2] = ya.z; sAcc[w][f+3] = ya.w;
                sAcc[w][DIN+f+0] = yb.x; sAcc[w][DIN+f+1] = yb.y;
                sAcc[w][DIN+f+2] = yb.z; sAcc[w][DIN+f+3] = yb.w;
            }
            __syncwarp();
            msg = 0.f;
            #pragma unroll
            for (int i = 0; i < DIN; i++){
                msg = fmaf(sAcc[w][i],     sA[i*32+lane], msg);
                msg = fmaf(sAcc[w][DIN+i], sB[i*32+lane], msg);
            }
        } else {
            int shift = 16 + (LAYER << 3);
            float4 acc = {0,0,0,0};
            for (int base = s; base < e1; base += 4){
                int i = base + slot;
                if (i < e1){
                    uint2 pl = __ldcg(&g_ebuf[i]);
                    int u = pl.x & 0xFFFF; int kk = (pl.x >> shift) & 0xFF;
                    float a = __uint_as_float(pl.y);
                    const float4* row = (const float4*)(g_PQ + ((size_t)(kk*Nn + u))*64);
                    float4 p = row[c], q = row[8+c];
                    acc.x = fmaf(a, p.x, acc.x) + q.x;
                    acc.y = fmaf(a, p.y, acc.y) + q.y;
                    acc.z = fmaf(a, p.z, acc.z) + q.z;
                    acc.w = fmaf(a, p.w, acc.w) + q.w;
                }
            }
            #pragma unroll
            for (int off = 8; off < 32; off <<= 1){
                acc.x += __shfl_xor_sync(FULL, acc.x, off);
                acc.y += __shfl_xor_sync(FULL, acc.y, off);
                acc.z += __shfl_xor_sync(FULL, acc.z, off);
                acc.w += __shfl_xor_sync(FULL, acc.w, off);
            }
            if (lane < 8){
                int f = lane*4;
                sAcc[w][f+0] = acc.x; sAcc[w][f+1] = acc.y;
                sAcc[w][f+2] = acc.z; sAcc[w][f+3] = acc.w;
            }
            __syncwarp();
            msg = sAcc[w][lane];
        }

        float inv = 1.f / fmaxf((float)(e1 - s), 1.f);
        float xv = (lane < DIN) ? xin[(size_t)v*DIN + lane] : 0.f;
        float rt = 0.f;
        #pragma unroll
        for (int i = 0; i < DIN; i++)
            rt = fmaf(__shfl_sync(FULL, xv, i), sR[i*32+lane], rt);
        float o = rt + msg*inv + sBi[lane];
        hout[(size_t)v*32 + lane] = o;
        accS += o;
        accQ = fmaf(o, o, accQ);
    }
    atomicAdd(&ssum[lane], accS);
    atomicAdd(&ssq[lane], accQ);
    __syncthreads();
    if (t < 32){
        atomicAdd(&g_stats[LAYER*64 + t],      ssum[t]);
        atomicAdd(&g_stats[LAYER*64 + 32 + t], ssq[t]);
    }
}

// ==== single persistent mega-kernel ====
__global__ void __launch_bounds__(256, 4)
k_mega(const float* __restrict__ x, const float* __restrict__ attr,
       const float* __restrict__ edft, const int* __restrict__ src,
       const int* __restrict__ dst, const int* __restrict__ batch,
       const float* l0w1, const float* l0b1, const float* l0w2, const float* l0b2,
       const float* l0root, const float* l0bias, const float* l0g, const float* l0be,
       const float* l1w1, const float* l1b1, const float* l1w2, const float* l1b2,
       const float* l1root, const float* l1bias, const float* l1g, const float* l1be,
       const float* mw1, const float* mb1, const float* mw2, const float* mb2,
       float* out)
{
    __shared__ float sW0[1024], sW1[1024], sW2[1024];
    __shared__ float sSc[32], sSh[32], sBi[32], ssum[32], ssq[32];
    __shared__ float sAcc[8][64];
    int t = threadIdx.x, lane = t & 31;

    // -------- P0: zero accumulators (block 0) + buildAB + edge classify/hist/deg --------
    if (blockIdx.x == 0){
        for (int i = t; i < 4*Hh; i += 256) g_stats[i] = 0.f;
        for (int i = t; i < Gg*Hh; i += 256) g_pool[i] = 0.f;
        if (t < Gg) g_pcnt[t] = 0;
    }
    for (int unit = blockIdx.x; unit < 2*NK + EDGE_BLKS; unit += gridDim.x){
        __syncthreads();
        if (unit < 2*NK){
            int layer = (unit >= NK);
            int k = unit - layer*NK;
            int D = layer ? (Hh*Hh) : (D0*Hh);
            float* A = layer ? g_A1 : g_A0;
            float* B = layer ? g_B1 : g_B0;
            const float* ew1 = layer ? l1w1 : l0w1;
            const float* eb1 = layer ? l1b1 : l0b1;
            const float* ew2 = layer ? l1w2 : l0w2;
            const float* eb2 = layer ? l1b2 : l0b2;
            float* sw = sW0; float* sb = sW0 + 32; int* sr = (int*)sW1;
            if (t < 32){
                float wj = ew1[t], bj = eb1[t], tv; int r;
                rank32(wj, bj, tv, r, t);
                sw[t] = wj; sb[t] = bj; sr[t] = r;
            }
            __syncthreads();
            for (int d = t; d < D; d += 256){
                float a = 0.f, b = eb2[d];
                for (int j = 0; j < 32; j++){
                    float wj = sw[j];
                    bool act = (wj > 0.f) ? (k > sr[j]) : ((wj < 0.f) ? (k <= sr[j]) : (sb[j] > 0.f));
                    if (act){ float w2 = ew2[j*D+d]; a += wj*w2; b += sb[j]*w2; }
                }
                A[k*D+d] = a; B[k*D+d] = b;
            }
        } else {
            float* st0 = sW0; float* st1 = sW0 + 32; int* sh = (int*)sW1;
            if (t < 32){ float tv; int r; rank32(l0w1[t], l0b1[t], tv, r, t); st0[r] = tv; }
            else if (t < 64){ int j = t-32; float tv; int r; rank32(l1w1[j], l1b1[j], tv, r, j); st1[r] = tv; }
            if (t < 2*NK) sh[t] = 0;
            __syncthreads();
            int e = (unit - 2*NK)*256 + t;
            bool valid = (e < Ee);
            float a = valid ? attr[e] : -FLT_MAX;
            int k0 = 0, k1 = 0;
            #pragma unroll
            for (int step = 16; step > 0; step >>= 1){
                if (st0[k0 + step - 1] <= a) k0 += step;
                if (st1[k1 + step - 1] <= a) k1 += step;
            }
            k0 += (st0[k0] <= a);   // counts range [0,32]
            k1 += (st1[k1] <= a);
            if (valid) atomicAdd(&g_deg[dst[e]], 1);
            int key0 = valid ? k0 : -1;
            unsigned m0 = __match_any_sync(FULL, key0);
            if (valid && lane == (__ffs(m0)-1)) atomicAdd(&sh[k0], __popc(m0));
            int key1 = valid ? k1 : -1;
            unsigned m1 = __match_any_sync(FULL, key1);
            if (valid && lane == (__ffs(m1)-1)) atomicAdd(&sh[NK+k1], __popc(m1));
            __syncthreads();
            if (t < 2*NK && sh[t]) atomicAdd(&g_hist[t], sh[t]);
        }
    }
    gridbar(0);

    // -------- P1: segment allocation + live-interval detect --------
    for (int unit = blockIdx.x; unit < ALLOC_UNITS; unit += gridDim.x){
        int i = unit*256 + t;
        int d = (i < Nn) ? g_deg[i] : 0;
        int sc = d;
        #pragma unroll
        for (int off = 1; off < 32; off <<= 1){
            int y = __shfl_up_sync(FULL, sc, off);
            if (lane >= off) sc += y;
        }
        int tot = __shfl_sync(FULL, sc, 31);
        int base = 0;
        if (lane == 31 && tot) base = atomicAdd(&g_total, tot);
        base = __shfl_sync(FULL, base, 31);
        if (i < Nn){
            int my = base + sc - d;
            g_off[i] = my; g_cur[i] = my; g_end[i] = my + d;
            g_deg[i] = 0;
        }
    }
    if (blockIdx.x == 0 && t < 2){
        int bb = t*NK, n = 0, kl = 0;
        for (int k = 0; k < NK; k++) if (g_hist[bb+k] > 0){ n++; kl = k; }
        g_nlive[t] = n; g_klive[t] = kl;
    }
    gridbar(1);

    int nl0 = g_nlive[0], kl0 = g_klive[0];
    int nl1 = g_nlive[1], kl1 = g_klive[1];
    bool fastboth = (nl0 == 1) && (nl1 == 1);

    // -------- P2: CSR fill (k recomputed on demand in general path) + PQ0 (general) --------
    if (!fastboth){
        float* st0 = sW0; float* st1 = sW0 + 32;
        if (t < 32){ float tv; int r; rank32(l0w1[t], l0b1[t], tv, r, t); st0[r] = tv; }
        else if (t < 64){ int j = t-32; float tv; int r; rank32(l1w1[j], l1b1[j], tv, r, j); st1[r] = tv; }
        __syncthreads();
    }
    for (int unit = blockIdx.x; unit < EDGE_BLKS; unit += gridDim.x){
        int e = unit*256 + t;
        if (e < Ee){
            float a = attr[e];
            unsigned px = (unsigned)src[e];
            if (!fastboth){
                const float* st0 = sW0; const float* st1 = sW0 + 32;
                int k0 = 0, k1 = 0;
                #pragma unroll
                for (int step = 16; step > 0; step >>= 1){
                    if (st0[k0 + step - 1] <= a) k0 += step;
                    if (st1[k1 + step - 1] <= a) k1 += step;
                }
                k0 += (st0[k0] <= a);
                k1 += (st1[k1] <= a);
                px |= ((unsigned)k0 << 16) | ((unsigned)k1 << 24);
            }
            uint2 pl; pl.x = px; pl.y = __float_as_uint(a);
            int p = atomicAdd(&g_cur[dst[e]], 1);
            g_ebuf[p] = pl;
        }
    }
    if (nl0 > 1){
        int w = t >> 5;
        for (int u = blockIdx.x*8 + w; u < Nn; u += gridDim.x*8){
            float xv_l = (lane < D0) ? __ldg(x + (size_t)u*D0 + lane) : 0.f;
            for (int k = 0; k < NK; k++){
                if (g_hist[k] == 0) continue;
                float p = 0.f, q = 0.f;
                for (int i = 0; i < D0; i++){
                    float xv = __shfl_sync(FULL, xv_l, i);
                    p = fmaf(xv, g_A0[k*D0*Hh + i*Hh + lane], p);
                    q = fmaf(xv, g_B0[k*D0*Hh + i*Hh + lane], q);
                }
                size_t ro = ((size_t)(k*Nn + u))*64;
                g_PQ[ro + lane] = p;
                g_PQ[ro + 32 + lane] = q;
            }
        }
    }
    gridbar(2);

    // -------- P3: aggregation layer 0 (raw x in, raw h out + stats0) --------
    agg_phase<D0,0>(x, l0root, l0bias, g_h,
                    sW0, sW1, sW2, sBi, ssum, ssq, sAcc, nl0, kl0);
    gridbar(3);

    // -------- P3a: hn = relu(BN0(h)) once; + PQ1 from hn (general path) --------
    __syncthreads();
    if (t < 32){
        float mu  = __ldcg(&g_stats[t])    * (1.f/(float)Nn);
        float var = __ldcg(&g_stats[32+t]) * (1.f/(float)Nn) - mu*mu;
        float sc  = rsqrtf(var + EPSI) * __ldg(l0g + t);
        sSc[t] = sc;
        sSh[t] = __ldg(l0be + t) - mu*sc;
    }
    __syncthreads();
    for (int idx = blockIdx.x*256 + t; idx < Nn*Hh; idx += gridDim.x*256){
        int f = idx & 31;
        g_hn[idx] = fmaxf(g_h[idx]*sSc[f] + sSh[f], 0.f);
    }
    gridbar(4);
    if (nl1 > 1){
        int w = t >> 5;
        for (int u = blockIdx.x*8 + w; u < Nn; u += gridDim.x*8){
            float xv_l = g_hn[(size_t)u*32 + lane];
            for (int k = 0; k < NK; k++){
                if (g_hist[NK + k] == 0) continue;
                float p = 0.f, q = 0.f;
                for (int i = 0; i < Hh; i++){
                    float xv = __shfl_sync(FULL, xv_l, i);
                    p = fmaf(xv, g_A1[k*Hh*Hh + i*Hh + lane], p);
                    q = fmaf(xv, g_B1[k*Hh*Hh + i*Hh + lane], q);
                }
                size_t ro = ((size_t)(k*Nn + u))*64;
                g_PQ[ro + lane] = p;
                g_PQ[ro + 32 + lane] = q;
            }
        }
        gridbar(5);
    }

    // -------- P4: aggregation layer 1 (hn in, h2 -> g_h reuse + stats1) --------
    agg_phase<Hh,1>(g_hn, l1root, l1bias, g_h,
                    sW0, sW1, sW2, sBi, ssum, ssq, sAcc, nl1, kl1);
    gridbar(6);

    // -------- P5: BN1 + ReLU + pool --------
    __syncthreads();
    if (t < 32){
        float mu  = __ldcg(&g_stats[64+t]) * (1.f/(float)Nn);
        float var = __ldcg(&g_stats[96+t]) * (1.f/(float)Nn) - mu*mu;
        float sc  = rsqrtf(var + EPSI) * __ldg(l1g + t);
        sSc[t] = sc;
        sSh[t] = __ldg(l1be + t) - mu*sc;
    }
    __syncthreads();
    for (int idx = blockIdx.x*256 + t; idx < Nn*Hh; idx += gridDim.x*256){
        int f = idx & 31, v = idx >> 5;
        float xv = fmaxf(g_h[idx]*sSc[f] + sSh[f], 0.f);
        int g = batch[v];
        atomicAdd(&g_pool[g*Hh + f], xv);
        if (f == 0) atomicAdd(&g_pcnt[g], 1);
    }
    gridbar(7);

    // -------- P6: readout MLP + cleanup (block 0) --------
    if (blockIdx.x == 0){
        if (t < 2*NK) g_hist[t] = 0;
        if (t == 255) g_total = 0;
        if (t < Gg){
            float zin[Hh+1];
            float inv = 1.f / fmaxf((float)__ldcg(&g_pcnt[t]), 1.f);
            for (int i = 0; i < Hh; i++) zin[i] = __ldcg(&g_pool[t*Hh+i])*inv;
            zin[Hh] = edft[t];
            float o = mb2[0];
            for (int j = 0; j < 64; j++){
                float hsum = mb1[j];
                #pragma unroll
                for (int i = 0; i < Hh+1; i++) hsum = fmaf(zin[i], mw1[i*64+j], hsum);
                o = fmaf(fmaxf(hsum, 0.f), mw2[j], o);
            }
            out[t] = o;
        }
    }
}

extern "C" void kernel_launch(void* const* d_in, const int* in_sizes, int n_in,
                              void* d_out, int out_size){
    const float* x     = (const float*)d_in[0];
    const float* attr  = (const float*)d_in[1];
    const float* edft  = (const float*)d_in[2];
    const int*   src   = (const int*)  d_in[3];
    const int*   dst   = (const int*)  d_in[4];
    const int*   batch = (const int*)  d_in[5];
    const float* l0w1=(const float*)d_in[6],  *l0b1=(const float*)d_in[7];
    const float* l0w2=(const float*)d_in[8],  *l0b2=(const float*)d_in[9];
    const float* l0root=(const float*)d_in[10],*l0bias=(const float*)d_in[11];
    const float* l0g=(const float*)d_in[12],  *l0be=(const float*)d_in[13];
    const float* l1w1=(const float*)d_in[14], *l1b1=(const float*)d_in[15];
    const float* l1w2=(const float*)d_in[16], *l1b2=(const float*)d_in[17];
    const float* l1root=(const float*)d_in[18],*l1bias=(const float*)d_in[19];
    const float* l1g=(const float*)d_in[20],  *l1be=(const float*)d_in[21];
    const float* mw1=(const float*)d_in[22],  *mb1=(const float*)d_in[23];
    const float* mw2=(const float*)d_in[24],  *mb2=(const float*)d_in[25];
    float* out = (float*)d_out;

    int dev = 0;
    cudaGetDevice(&dev);
    int nsm = 0;
    cudaDeviceGetAttribute(&nsm, cudaDevAttrMultiProcessorCount, dev);
    if (nsm <= 0) nsm = 148;
    int nb = 0;
    cudaOccupancyMaxActiveBlocksPerMultiprocessor(&nb, k_mega, 256, 0);
    if (nb < 1) nb = 1;
    int grid = nsm * nb;

    k_mega<<<grid, 256>>>(x, attr, edft, src, dst, batch,
                          l0w1, l0b1, l0w2, l0b2, l0root, l0bias, l0g, l0be,
                          l1w1, l1b1, l1w2, l1b2, l1root, l1bias, l1g, l1be,
                          mw1, mb1, mw2, mb2, out);
}

// round 13
// speedup vs baseline: 1.2403x; 1.1325x over previous
#include <cuda_runtime.h>
#include <cfloat>

#define Nn 20000
#define Ee 320000
#define Gg 64
#define D0 16
#define Hh 32
#define NK 33
#define EPSI 1e-5f
#define FULL 0xffffffffu
#define TPB 1024

// ---------------- static device scratch (zero-init at load; self-cleaning across replays) ----------------
__device__ float g_A0[NK*D0*Hh], g_B0[NK*D0*Hh];
__device__ float g_A1[NK*Hh*Hh], g_B1[NK*Hh*Hh];
__device__ int g_deg[Nn];               // zeroed in alloc phase after read
__device__ int g_total;                 // zeroed in final phase each run
__device__ int g_off[Nn], g_end[Nn], g_cur[Nn];
__device__ int g_nlive[2], g_klive[2];  // overwritten each run
__device__ float g_bmin[1024], g_bmax[1024];   // per-block attr min/max (overwritten each run)
__device__ uint2 g_ebuf[Ee];
__device__ __align__(16) float g_PQ[(size_t)NK*Nn*64];   // general path only
__device__ __align__(16) float g_h[Nn*Hh], g_hn[Nn*Hh];
__device__ float g_stats[4*Hh];         // [sum0|sq0|sum1|sq1]
__device__ float g_pool[Gg*Hh];
__device__ int   g_pcnt[Gg];
// sense-reversing grid barriers (replay-safe)
__device__ int g_bcnt[8];
__device__ volatile int g_bsense[8];

__device__ __forceinline__ void gridbar(int i){
    __syncthreads();
    if (threadIdx.x == 0){
        int sense = g_bsense[i];
        __threadfence();
        if (atomicAdd(&g_bcnt[i], 1) == (int)gridDim.x - 1){
            g_bcnt[i] = 0;
            __threadfence();
            g_bsense[i] = sense ^ 1;
        } else {
            while (g_bsense[i] == sense) __nanosleep(64);
            __threadfence();
        }
    }
    __syncthreads();
}

__device__ __forceinline__ void rank32(float wj, float bj, float& t, int& r, int j){
    t = (wj != 0.0f) ? (-bj / wj) : FLT_MAX;
    r = 0;
    #pragma unroll
    for (int m = 0; m < 32; m++){
        float tm = __shfl_sync(FULL, t, m);
        r += (tm < t || (tm == t && m < j));
    }
}

// ==== aggregation phase (inputs pre-normalized); 32 warps/block ====
template<int DIN, int LAYER>
__device__ __forceinline__ void agg_phase(
    const float* __restrict__ xin, const float* __restrict__ root,
    const float* __restrict__ bias, float* __restrict__ hout,
    float* sA, float* sB, float* sR, float* sBi,
    float* ssum, float* ssq, float (*sAcc)[64], int nlive, int kl)
{
    constexpr int NC = DIN/4;
    constexpr int NS = 32/NC;
    int t = threadIdx.x, lane = t & 31, w = t >> 5;
    __syncthreads();
    if (t < 32){ ssum[t] = 0.f; ssq[t] = 0.f; sBi[t] = __ldg(bias + t); }
    for (int d = t; d < DIN*32; d += TPB) sR[d] = __ldg(root + d);
    if (nlive == 1){
        const float* A = LAYER ? g_A1 : g_A0;
        const float* B = LAYER ? g_B1 : g_B0;
        for (int d = t; d < DIN*32; d += TPB){
            sA[d] = A[kl*DIN*32 + d];
            sB[d] = B[kl*DIN*32 + d];
        }
    }
    __syncthreads();

    int slot, c;
    if (nlive == 1){ slot = lane / NC; c = lane % NC; }
    else           { slot = lane >> 3; c = lane & 7; }
    const float4* x4 = (const float4*)xin;
    float accS = 0.f, accQ = 0.f;

    for (int v = blockIdx.x*32 + w; v < Nn; v += gridDim.x*32){
        int s = g_off[v], e1 = g_end[v];
        float msg;
        if (nlive == 1){
            float4 ya0={0,0,0,0}, yb0={0,0,0,0}, ya1={0,0,0,0}, yb1={0,0,0,0};
            int i0 = s + slot, i1 = i0 + NS;
            bool v0 = i0 < e1, v1 = i1 < e1;
            uint2 p0 = make_uint2(0,0), p1 = make_uint2(0,0);
            if (v0) p0 = __ldcg(&g_ebuf[i0]);
            if (v1) p1 = __ldcg(&g_ebuf[i1]);
            while (__any_sync(FULL, v0)){
                int n0 = i0 + 2*NS, n1 = i1 + 2*NS;
                bool w0 = n0 < e1, w1 = n1 < e1;
                uint2 q0 = make_uint2(0,0), q1 = make_uint2(0,0);
                if (w0) q0 = __ldcg(&g_ebuf[n0]);
                if (w1) q1 = __ldcg(&g_ebuf[n1]);
                if (v0){
                    int u = p0.x & 0xFFFF; float a = __uint_as_float(p0.y);
                    float4 xc = x4[(size_t)u*NC + c];
                    ya0.x = fmaf(a, xc.x, ya0.x); yb0.x += xc.x;
                    ya0.y = fmaf(a, xc.y, ya0.y); yb0.y += xc.y;
                    ya0.z = fmaf(a, xc.z, ya0.z); yb0.z += xc.z;
                    ya0.w = fmaf(a, xc.w, ya0.w); yb0.w += xc.w;
                }
                if (v1){
                    int u = p1.x & 0xFFFF; float a = __uint_as_float(p1.y);
                    float4 xc = x4[(size_t)u*NC + c];
                    ya1.x = fmaf(a, xc.x, ya1.x); yb1.x += xc.x;
                    ya1.y = fmaf(a, xc.y, ya1.y); yb1.y += xc.y;
                    ya1.z = fmaf(a, xc.z, ya1.z); yb1.z += xc.z;
                    ya1.w = fmaf(a, xc.w, ya1.w); yb1.w += xc.w;
                }
                i0 = n0; i1 = n1; v0 = w0; v1 = w1; p0 = q0; p1 = q1;
            }
            float4 ya, yb;
            ya.x = ya0.x + ya1.x; ya.y = ya0.y + ya1.y;
            ya.z = ya0.z + ya1.z; ya.w = ya0.w + ya1.w;
            yb.x = yb0.x + yb1.x; yb.y = yb0.y + yb1.y;
            yb.z = yb0.z + yb1.z; yb.w = yb0.w + yb1.w;
            #pragma unroll
            for (int off = NC; off < 32; off <<= 1){
                ya.x += __shfl_xor_sync(FULL, ya.x, off);
                ya.y += __shfl_xor_sync(FULL, ya.y, off);
                ya.z += __shfl_xor_sync(FULL, ya.z, off);
                ya.w += __shfl_xor_sync(FULL, ya.w, off);
                yb.x += __shfl_xor_sync(FULL, yb.x, off);
                yb.y += __shfl_xor_sync(FULL, yb.y, off);
                yb.z += __shfl_xor_sync(FULL, yb.z, off);
                yb.w += __shfl_xor_sync(FULL, yb.w, off);
            }
            if (lane < NC){
                int f = lane*4;
                sAcc[w][f+0] = ya.x; sAcc[w][f+1] = ya.y;
                sAcc[w][f+2] = ya.z; sAcc[w][f+3] = ya.w;
                sAcc[w][DIN+f+0] = yb.x; sAcc[w][DIN+f+1] = yb.y;
                sAcc[w][DIN+f+2] = yb.z; sAcc[w][DIN+f+3] = yb.w;
            }
            __syncwarp();
            msg = 0.f;
            #pragma unroll
            for (int i = 0; i < DIN; i++){
                msg = fmaf(sAcc[w][i],     sA[i*32+lane], msg);
                msg = fmaf(sAcc[w][DIN+i], sB[i*32+lane], msg);
            }
        } else {
            int shift = 16 + (LAYER << 3);
            float4 acc = {0,0,0,0};
            for (int base = s; base < e1; base += 4){
                int i = base + slot;
                if (i < e1){
                    uint2 pl = __ldcg(&g_ebuf[i]);
                    int u = pl.x & 0xFFFF; int kk = (pl.x >> shift) & 0xFF;
                    float a = __uint_as_float(pl.y);
                    const float4* row = (const float4*)(g_PQ + ((size_t)(kk*Nn + u))*64);
                    float4 p = row[c], q = row[8+c];
                    acc.x = fmaf(a, p.x, acc.x) + q.x;
                    acc.y = fmaf(a, p.y, acc.y) + q.y;
                    acc.z = fmaf(a, p.z, acc.z) + q.z;
                    acc.w = fmaf(a, p.w, acc.w) + q.w;
                }
            }
            #pragma unroll
            for (int off = 8; off < 32; off <<= 1){
                acc.x += __shfl_xor_sync(FULL, acc.x, off);
                acc.y += __shfl_xor_sync(FULL, acc.y, off);
                acc.z += __shfl_xor_sync(FULL, acc.z, off);
                acc.w += __shfl_xor_sync(FULL, acc.w, off);
            }
            if (lane < 8){
                int f = lane*4;
                sAcc[w][f+0] = acc.x; sAcc[w][f+1] = acc.y;
                sAcc[w][f+2] = acc.z; sAcc[w][f+3] = acc.w;
            }
            __syncwarp();
            msg = sAcc[w][lane];
        }

        float inv = 1.f / fmaxf((float)(e1 - s), 1.f);
        float xv = (lane < DIN) ? xin[(size_t)v*DIN + lane] : 0.f;
        float rt = 0.f;
        #pragma unroll
        for (int i = 0; i < DIN; i++)
            rt = fmaf(__shfl_sync(FULL, xv, i), sR[i*32+lane], rt);
        float o = rt + msg*inv + sBi[lane];
        hout[(size_t)v*32 + lane] = o;
        accS += o;
        accQ = fmaf(o, o, accQ);
    }
    atomicAdd(&ssum[lane], accS);
    atomicAdd(&ssq[lane], accQ);
    __syncthreads();
    if (t < 32){
        atomicAdd(&g_stats[LAYER*64 + t],      ssum[t]);
        atomicAdd(&g_stats[LAYER*64 + 32 + t], ssq[t]);
    }
}

// ==== single persistent mega-kernel, 1024 threads/block, grid = #SMs ====
__global__ void __launch_bounds__(TPB, 1)
k_mega(const float* __restrict__ x, const float* __restrict__ attr,
       const float* __restrict__ edft, const int* __restrict__ src,
       const int* __restrict__ dst, const int* __restrict__ batch,
       const float* l0w1, const float* l0b1, const float* l0w2, const float* l0b2,
       const float* l0root, const float* l0bias, const float* l0g, const float* l0be,
       const float* l1w1, const float* l1b1, const float* l1w2, const float* l1b2,
       const float* l1root, const float* l1bias, const float* l1g, const float* l1be,
       const float* mw1, const float* mb1, const float* mw2, const float* mb2,
       float* out)
{
    __shared__ float sW0[1024], sW1[1024], sW2[1024];
    __shared__ float sSc[32], sSh[32], sBi[32], ssum[32], ssq[32];
    __shared__ float sMin[32], sMax[32];
    __shared__ float sAcc[32][64];
    int t = threadIdx.x, lane = t & 31, w = t >> 5;

    // -------- P0: zeroing (block 0) + buildAB (blocks <2NK) + edge deg/minmax (all) --------
    if (blockIdx.x == 0){
        for (int i = t; i < 4*Hh; i += TPB) g_stats[i] = 0.f;
        for (int i = t; i < Gg*Hh; i += TPB) g_pool[i] = 0.f;
        if (t < Gg) g_pcnt[t] = 0;
    }
    if (blockIdx.x < 2*NK){
        int layer = (blockIdx.x >= NK);
        int k = blockIdx.x - layer*NK;
        int D = layer ? (Hh*Hh) : (D0*Hh);
        float* A = layer ? g_A1 : g_A0;
        float* B = layer ? g_B1 : g_B0;
        const float* ew1 = layer ? l1w1 : l0w1;
        const float* eb1 = layer ? l1b1 : l0b1;
        const float* ew2 = layer ? l1w2 : l0w2;
        const float* eb2 = layer ? l1b2 : l0b2;
        float* sw = sW0; float* sb = sW0 + 32; int* sr = (int*)sW1;
        if (t < 32){
            float wj = ew1[t], bj = eb1[t], tv; int r;
            rank32(wj, bj, tv, r, t);
            sw[t] = wj; sb[t] = bj; sr[t] = r;
        }
        __syncthreads();
        for (int d = t; d < D; d += TPB){
            float a = 0.f, b = eb2[d];
            for (int j = 0; j < 32; j++){
                float wj = sw[j];
                bool act = (wj > 0.f) ? (k > sr[j]) : ((wj < 0.f) ? (k <= sr[j]) : (sb[j] > 0.f));
                if (act){ float w2 = ew2[j*D+d]; a += wj*w2; b += sb[j]*w2; }
            }
            A[k*D+d] = a; B[k*D+d] = b;
        }
        __syncthreads();
    }
    // edge pass: degree count + attr min/max (register-only, block reduce)
    {
        float amn = FLT_MAX, amx = -FLT_MAX;
        for (int e = blockIdx.x*TPB + t; e < Ee; e += gridDim.x*TPB){
            float a = attr[e];
            amn = fminf(amn, a); amx = fmaxf(amx, a);
            atomicAdd(&g_deg[dst[e]], 1);
        }
        #pragma unroll
        for (int off = 16; off; off >>= 1){
            amn = fminf(amn, __shfl_xor_sync(FULL, amn, off));
            amx = fmaxf(amx, __shfl_xor_sync(FULL, amx, off));
        }
        if (lane == 0){ sMin[w] = amn; sMax[w] = amx; }
        __syncthreads();
        if (t < 32){
            amn = sMin[t]; amx = sMax[t];
            #pragma unroll
            for (int off = 16; off; off >>= 1){
                amn = fminf(amn, __shfl_xor_sync(FULL, amn, off));
                amx = fmaxf(amx, __shfl_xor_sync(FULL, amx, off));
            }
            if (t == 0){ g_bmin[blockIdx.x] = amn; g_bmax[blockIdx.x] = amx; }
        }
    }
    gridbar(0);

    // -------- P1: segment allocation + interval-range detect from attr min/max --------
    if (blockIdx.x == 0 && t < 32){
        float amn = FLT_MAX, amx = -FLT_MAX;
        for (int b = lane; b < (int)gridDim.x; b += 32){
            amn = fminf(amn, g_bmin[b]); amx = fmaxf(amx, g_bmax[b]);
        }
        #pragma unroll
        for (int off = 16; off; off >>= 1){
            amn = fminf(amn, __shfl_xor_sync(FULL, amn, off));
            amx = fmaxf(amx, __shfl_xor_sync(FULL, amx, off));
        }
        // layer 0 thresholds: k(a) = popc(ballot(t_j <= a))
        float wj = l0w1[lane], bj = l0b1[lane];
        float tj = (wj != 0.f) ? (-bj/wj) : FLT_MAX;
        int kmin = __popc(__ballot_sync(FULL, tj <= amn));
        int kmax = __popc(__ballot_sync(FULL, tj <= amx));
        if (lane == 0){ g_klive[0] = kmin; g_nlive[0] = kmax - kmin + 1; }
        wj = l1w1[lane]; bj = l1b1[lane];
        tj = (wj != 0.f) ? (-bj/wj) : FLT_MAX;
        kmin = __popc(__ballot_sync(FULL, tj <= amn));
        kmax = __popc(__ballot_sync(FULL, tj <= amx));
        if (lane == 0){ g_klive[1] = kmin; g_nlive[1] = kmax - kmin + 1; }
    }
    for (int base = blockIdx.x*TPB; base < Nn; base += gridDim.x*TPB){
        int i = base + t;
        int d = (i < Nn) ? g_deg[i] : 0;
        int sc = d;
        #pragma unroll
        for (int off = 1; off < 32; off <<= 1){
            int y = __shfl_up_sync(FULL, sc, off);
            if (lane >= off) sc += y;
        }
        int tot = __shfl_sync(FULL, sc, 31);
        int base2 = 0;
        if (lane == 31 && tot) base2 = atomicAdd(&g_total, tot);
        base2 = __shfl_sync(FULL, base2, 31);
        if (i < Nn){
            int my = base2 + sc - d;
            g_off[i] = my; g_cur[i] = my; g_end[i] = my + d;
            g_deg[i] = 0;
        }
    }
    gridbar(1);

    int nl0 = g_nlive[0], kl0 = g_klive[0];
    int nl1 = g_nlive[1], kl1 = g_klive[1];
    bool fastboth = (nl0 == 1) && (nl1 == 1);

    // -------- P2: CSR fill (per-edge k recomputed only in general path) + PQ0 (general) --------
    if (!fastboth){
        float* st0 = sW0; float* st1 = sW0 + 32;
        if (t < 32){ float tv; int r; rank32(l0w1[t], l0b1[t], tv, r, t); st0[r] = tv; }
        else if (t < 64){ int j = t-32; float tv; int r; rank32(l1w1[j], l1b1[j], tv, r, j); st1[r] = tv; }
        __syncthreads();
    }
    for (int e = blockIdx.x*TPB + t; e < Ee; e += gridDim.x*TPB){
        float a = attr[e];
        unsigned px = (unsigned)src[e];
        if (!fastboth){
            const float* st0 = sW0; const float* st1 = sW0 + 32;
            int k0 = 0, k1 = 0;
            #pragma unroll
            for (int step = 16; step > 0; step >>= 1){
                if (st0[k0 + step - 1] <= a) k0 += step;
                if (st1[k1 + step - 1] <= a) k1 += step;
            }
            k0 += (st0[k0] <= a);
            k1 += (st1[k1] <= a);
            px |= ((unsigned)k0 << 16) | ((unsigned)k1 << 24);
        }
        uint2 pl; pl.x = px; pl.y = __float_as_uint(a);
        int p = atomicAdd(&g_cur[dst[e]], 1);
        g_ebuf[p] = pl;
    }
    if (nl0 > 1){
        for (int u = blockIdx.x*32 + w; u < Nn; u += gridDim.x*32){
            float xv_l = (lane < D0) ? __ldg(x + (size_t)u*D0 + lane) : 0.f;
            for (int k = kl0; k < kl0 + nl0; k++){
                float p = 0.f, q = 0.f;
                for (int i = 0; i < D0; i++){
                    float xv = __shfl_sync(FULL, xv_l, i);
                    p = fmaf(xv, g_A0[k*D0*Hh + i*Hh + lane], p);
                    q = fmaf(xv, g_B0[k*D0*Hh + i*Hh + lane], q);
                }
                size_t ro = ((size_t)(k*Nn + u))*64;
                g_PQ[ro + lane] = p;
                g_PQ[ro + 32 + lane] = q;
            }
        }
    }
    gridbar(2);

    // -------- P3: aggregation layer 0 --------
    agg_phase<D0,0>(x, l0root, l0bias, g_h,
                    sW0, sW1, sW2, sBi, ssum, ssq, sAcc, nl0, kl0);
    gridbar(3);

    // -------- P3a: hn = relu(BN0(h)) once --------
    __syncthreads();
    if (t < 32){
        float mu  = __ldcg(&g_stats[t])    * (1.f/(float)Nn);
        float var = __ldcg(&g_stats[32+t]) * (1.f/(float)Nn) - mu*mu;
        float sc  = rsqrtf(var + EPSI) * __ldg(l0g + t);
        sSc[t] = sc;
        sSh[t] = __ldg(l0be + t) - mu*sc;
    }
    __syncthreads();
    for (int idx = blockIdx.x*TPB + t; idx < Nn*Hh; idx += gridDim.x*TPB){
        int f = idx & 31;
        g_hn[idx] = fmaxf(g_h[idx]*sSc[f] + sSh[f], 0.f);
    }
    gridbar(4);
    if (nl1 > 1){
        for (int u = blockIdx.x*32 + w; u < Nn; u += gridDim.x*32){
            float xv_l = g_hn[(size_t)u*32 + lane];
            for (int k = kl1; k < kl1 + nl1; k++){
                float p = 0.f, q = 0.f;
                for (int i = 0; i < Hh; i++){
                    float xv = __shfl_sync(FULL, xv_l, i);
                    p = fmaf(xv, g_A1[k*Hh*Hh + i*Hh + lane], p);
                    q = fmaf(xv, g_B1[k*Hh*Hh + i*Hh + lane], q);
                }
                size_t ro = ((size_t)(k*Nn + u))*64;
                g_PQ[ro + lane] = p;
                g_PQ[ro + 32 + lane] = q;
            }
        }
        gridbar(5);
    }

    // -------- P4: aggregation layer 1 --------
    agg_phase<Hh,1>(g_hn, l1root, l1bias, g_h,
                    sW0, sW1, sW2, sBi, ssum, ssq, sAcc, nl1, kl1);
    gridbar(6);

    // -------- P5: BN1 + ReLU + pool --------
    __syncthreads();
    if (t < 32){
        float mu  = __ldcg(&g_stats[64+t]) * (1.f/(float)Nn);
        float var = __ldcg(&g_stats[96+t]) * (1.f/(float)Nn) - mu*mu;
        float sc  = rsqrtf(var + EPSI) * __ldg(l1g + t);
        sSc[t] = sc;
        sSh[t] = __ldg(l1be + t) - mu*sc;
    }
    __syncthreads();
    for (int idx = blockIdx.x*TPB + t; idx < Nn*Hh; idx += gridDim.x*TPB){
        int f = idx & 31, v = idx >> 5;
        float xv = fmaxf(g_h[idx]*sSc[f] + sSh[f], 0.f);
        int g = batch[v];
        atomicAdd(&g_pool[g*Hh + f], xv);
        if (f == 0) atomicAdd(&g_pcnt[g], 1);
    }
    gridbar(7);

    // -------- P6: readout MLP + cleanup (block 0) --------
    if (blockIdx.x == 0){
        if (t == TPB-1) g_total = 0;
        if (t < Gg){
            float zin[Hh+1];
            float inv = 1.f / fmaxf((float)__ldcg(&g_pcnt[t]), 1.f);
            for (int i = 0; i < Hh; i++) zin[i] = __ldcg(&g_pool[t*Hh+i])*inv;
            zin[Hh] = edft[t];
            float o = mb2[0];
            for (int j = 0; j < 64; j++){
                float hsum = mb1[j];
                #pragma unroll
                for (int i = 0; i < Hh+1; i++) hsum = fmaf(zin[i], mw1[i*64+j], hsum);
                o = fmaf(fmaxf(hsum, 0.f), mw2[j], o);
            }
            out[t] = o;
        }
    }
}

extern "C" void kernel_launch(void* const* d_in, const int* in_sizes, int n_in,
                              void* d_out, int out_size){
    const float* x     = (const float*)d_in[0];
    const float* attr  = (const float*)d_in[1];
    const float* edft  = (const float*)d_in[2];
    const int*   src   = (const int*)  d_in[3];
    const int*   dst   = (const int*)  d_in[4];
    const int*   batch = (const int*)  d_in[5];
    const float* l0w1=(const float*)d_in[6],  *l0b1=(const float*)d_in[7];
    const float* l0w2=(const float*)d_in[8],  *l0b2=(const float*)d_in[9];
    const float* l0root=(const float*)d_in[10],*l0bias=(const float*)d_in[11];
    const float* l0g=(const float*)d_in[12],  *l0be=(const float*)d_in[13];
    const float* l1w1=(const float*)d_in[14], *l1b1=(const float*)d_in[15];
    const float* l1w2=(const float*)d_in[16], *l1b2=(const float*)d_in[17];
    const float* l1root=(const float*)d_in[18],*l1bias=(const float*)d_in[19];
    const float* l1g=(const float*)d_in[20],  *l1be=(const float*)d_in[21];
    const float* mw1=(const float*)d_in[22],  *mb1=(const float*)d_in[23];
    const float* mw2=(const float*)d_in[24],  *mb2=(const float*)d_in[25];
    float* out = (float*)d_out;

    int dev = 0;
    cudaGetDevice(&dev);
    int nsm = 0;
    cudaDeviceGetAttribute(&nsm, cudaDevAttrMultiProcessorCount, dev);
    if (nsm <= 0) nsm = 148;
    int nb = 0;
    cudaOccupancyMaxActiveBlocksPerMultiprocessor(&nb, k_mega, TPB, 0);
    if (nb < 1) nb = 1;
    int grid = nsm * nb;
    if (grid > 1024) grid = 1024;   // g_bmin/g_bmax capacity

    k_mega<<<grid, TPB>>>(x, attr, edft, src, dst, batch,
                          l0w1, l0b1, l0w2, l0b2, l0root, l0bias, l0g, l0be,
                          l1w1, l1b1, l1w2, l1b2, l1root, l1bias, l1g, l1be,
                          mw1, mb1, mw2, mb2, out);
}

// round 14
// speedup vs baseline: 1.2959x; 1.0448x over previous
#include <cuda_runtime.h>
#include <cfloat>

#define Nn 20000
#define Ee 320000
#define Gg 64
#define D0 16
#define Hh 32
#define NK 33
#define EPSI 1e-5f
#define FULL 0xffffffffu
#define TPB 1024

// ---------------- static device scratch (zero-init at load; self-cleaning across replays) ----------------
__device__ float g_A0[NK*D0*Hh], g_B0[NK*D0*Hh];
__device__ float g_A1[NK*Hh*Hh], g_B1[NK*Hh*Hh];
__device__ int g_deg[Nn];               // zeroed in alloc phase after read
__device__ int g_rank[Ee];              // per-edge rank within its dst segment
__device__ int g_total;                 // zeroed in final phase each run
__device__ int g_off[Nn], g_end[Nn];
__device__ int g_nlive[2], g_klive[2];
__device__ float g_bmin[1024], g_bmax[1024];
__device__ uint2 g_ebuf[Ee];
__device__ __align__(16) float g_PQ[(size_t)NK*Nn*64];   // general path only
__device__ __align__(16) float g_h[Nn*Hh], g_hn[Nn*Hh];
__device__ float g_stats[4*Hh];
__device__ float g_pool[Gg*Hh];
__device__ int   g_pcnt[Gg];
__device__ int g_bcnt[8];
__device__ volatile int g_bsense[8];

__device__ __forceinline__ void gridbar(int i){
    __syncthreads();
    if (threadIdx.x == 0){
        int sense = g_bsense[i];
        __threadfence();
        if (atomicAdd(&g_bcnt[i], 1) == (int)gridDim.x - 1){
            g_bcnt[i] = 0;
            __threadfence();
            g_bsense[i] = sense ^ 1;
        } else {
            while (g_bsense[i] == sense) __nanosleep(64);
            __threadfence();
        }
    }
    __syncthreads();
}

__device__ __forceinline__ void rank32(float wj, float bj, float& t, int& r, int j){
    t = (wj != 0.0f) ? (-bj / wj) : FLT_MAX;
    r = 0;
    #pragma unroll
    for (int m = 0; m < 32; m++){
        float tm = __shfl_sync(FULL, t, m);
        r += (tm < t || (tm == t && m < j));
    }
}

// ==== aggregation phase: fast path pipelined across nodes ====
template<int DIN, int LAYER>
__device__ __forceinline__ void agg_phase(
    const float* __restrict__ xin, const float* __restrict__ root,
    const float* __restrict__ bias, float* __restrict__ hout,
    float* sA, float* sB, float* sR, float* sBi,
    float* ssum, float* ssq, float (*sAcc)[64], int nlive, int kl)
{
    constexpr int NC = DIN/4;
    constexpr int NS = 32/NC;
    int t = threadIdx.x, lane = t & 31, w = t >> 5;
    __syncthreads();
    if (t < 32){ ssum[t] = 0.f; ssq[t] = 0.f; sBi[t] = __ldg(bias + t); }
    for (int d = t; d < DIN*32; d += TPB) sR[d] = __ldg(root + d);
    if (nlive == 1){
        const float* A = LAYER ? g_A1 : g_A0;
        const float* B = LAYER ? g_B1 : g_B0;
        for (int d = t; d < DIN*32; d += TPB){
            sA[d] = A[kl*DIN*32 + d];
            sB[d] = B[kl*DIN*32 + d];
        }
    }
    __syncthreads();

    const float4* x4 = (const float4*)xin;
    float accS = 0.f, accQ = 0.f;
    int stride = gridDim.x*32;

    if (nlive == 1){
        int slot = lane / NC, c = lane % NC;
        int v = blockIdx.x*32 + w;
        int s = 0, e1 = 0;
        bool v0 = false, v1 = false;
        uint2 p0 = make_uint2(0,0), p1 = make_uint2(0,0);
        if (v < Nn){
            s = g_off[v]; e1 = g_end[v];
            int i0 = s + slot, i1 = i0 + NS;
            v0 = i0 < e1; v1 = i1 < e1;
            if (v0) p0 = __ldcg(&g_ebuf[i0]);
            if (v1) p1 = __ldcg(&g_ebuf[i1]);
        }
        while (v < Nn){
            // prefetch next node's segment bounds (resolves behind gather+epilogue)
            int nv = v + stride;
            int ns = 0, ne = 0;
            if (nv < Nn){ ns = g_off[nv]; ne = g_end[nv]; }

            float4 ya0={0,0,0,0}, yb0={0,0,0,0}, ya1={0,0,0,0}, yb1={0,0,0,0};
            int c0 = s + slot, c1 = c0 + NS;
            while (__any_sync(FULL, v0)){
                int n0 = c0 + 2*NS, n1 = c1 + 2*NS;
                bool w0 = n0 < e1, w1 = n1 < e1;
                uint2 q0 = make_uint2(0,0), q1 = make_uint2(0,0);
                if (w0) q0 = __ldcg(&g_ebuf[n0]);
                if (w1) q1 = __ldcg(&g_ebuf[n1]);
                if (v0){
                    int u = p0.x & 0xFFFF; float a = __uint_as_float(p0.y);
                    float4 xc = x4[(size_t)u*NC + c];
                    ya0.x = fmaf(a, xc.x, ya0.x); yb0.x += xc.x;
                    ya0.y = fmaf(a, xc.y, ya0.y); yb0.y += xc.y;
                    ya0.z = fmaf(a, xc.z, ya0.z); yb0.z += xc.z;
                    ya0.w = fmaf(a, xc.w, ya0.w); yb0.w += xc.w;
                }
                if (v1){
                    int u = p1.x & 0xFFFF; float a = __uint_as_float(p1.y);
                    float4 xc = x4[(size_t)u*NC + c];
                    ya1.x = fmaf(a, xc.x, ya1.x); yb1.x += xc.x;
                    ya1.y = fmaf(a, xc.y, ya1.y); yb1.y += xc.y;
                    ya1.z = fmaf(a, xc.z, ya1.z); yb1.z += xc.z;
                    ya1.w = fmaf(a, xc.w, ya1.w); yb1.w += xc.w;
                }
                c0 = n0; c1 = n1; v0 = w0; v1 = w1; p0 = q0; p1 = q1;
            }

            // prefetch next node's first payloads (resolve behind reduction+epilogue)
            int ni0 = ns + slot, ni1 = ni0 + NS;
            bool nv0 = (nv < Nn) && (ni0 < ne);
            bool nv1 = (nv < Nn) && (ni1 < ne);
            uint2 np0 = make_uint2(0,0), np1 = make_uint2(0,0);
            if (nv0) np0 = __ldcg(&g_ebuf[ni0]);
            if (nv1) np1 = __ldcg(&g_ebuf[ni1]);

            float4 ya, yb;
            ya.x = ya0.x + ya1.x; ya.y = ya0.y + ya1.y;
            ya.z = ya0.z + ya1.z; ya.w = ya0.w + ya1.w;
            yb.x = yb0.x + yb1.x; yb.y = yb0.y + yb1.y;
            yb.z = yb0.z + yb1.z; yb.w = yb0.w + yb1.w;
            #pragma unroll
            for (int off = NC; off < 32; off <<= 1){
                ya.x += __shfl_xor_sync(FULL, ya.x, off);
                ya.y += __shfl_xor_sync(FULL, ya.y, off);
                ya.z += __shfl_xor_sync(FULL, ya.z, off);
                ya.w += __shfl_xor_sync(FULL, ya.w, off);
                yb.x += __shfl_xor_sync(FULL, yb.x, off);
                yb.y += __shfl_xor_sync(FULL, yb.y, off);
                yb.z += __shfl_xor_sync(FULL, yb.z, off);
                yb.w += __shfl_xor_sync(FULL, yb.w, off);
            }
            if (lane < NC){
                int f = lane*4;
                sAcc[w][f+0] = ya.x; sAcc[w][f+1] = ya.y;
                sAcc[w][f+2] = ya.z; sAcc[w][f+3] = ya.w;
                sAcc[w][DIN+f+0] = yb.x; sAcc[w][DIN+f+1] = yb.y;
                sAcc[w][DIN+f+2] = yb.z; sAcc[w][DIN+f+3] = yb.w;
            }
            __syncwarp();
            float msg = 0.f;
            #pragma unroll
            for (int i = 0; i < DIN; i++){
                msg = fmaf(sAcc[w][i],     sA[i*32+lane], msg);
                msg = fmaf(sAcc[w][DIN+i], sB[i*32+lane], msg);
            }
            float inv = 1.f / fmaxf((float)(e1 - s), 1.f);
            float xv = (lane < DIN) ? xin[(size_t)v*DIN + lane] : 0.f;
            float rt = 0.f;
            #pragma unroll
            for (int i = 0; i < DIN; i++)
                rt = fmaf(__shfl_sync(FULL, xv, i), sR[i*32+lane], rt);
            float o = rt + msg*inv + sBi[lane];
            hout[(size_t)v*32 + lane] = o;
            accS += o;
            accQ = fmaf(o, o, accQ);

            v = nv; s = ns; e1 = ne; v0 = nv0; v1 = nv1; p0 = np0; p1 = np1;
        }
    } else {
        int slot = lane >> 3, c = lane & 7;
        int shift = 16 + (LAYER << 3);
        for (int v = blockIdx.x*32 + w; v < Nn; v += stride){
            int s = g_off[v], e1 = g_end[v];
            float4 acc = {0,0,0,0};
            for (int base = s; base < e1; base += 4){
                int i = base + slot;
                if (i < e1){
                    uint2 pl = __ldcg(&g_ebuf[i]);
                    int u = pl.x & 0xFFFF; int kk = (pl.x >> shift) & 0xFF;
                    float a = __uint_as_float(pl.y);
                    const float4* row = (const float4*)(g_PQ + ((size_t)(kk*Nn + u))*64);
                    float4 p = row[c], q = row[8+c];
                    acc.x = fmaf(a, p.x, acc.x) + q.x;
                    acc.y = fmaf(a, p.y, acc.y) + q.y;
                    acc.z = fmaf(a, p.z, acc.z) + q.z;
                    acc.w = fmaf(a, p.w, acc.w) + q.w;
                }
            }
            #pragma unroll
            for (int off = 8; off < 32; off <<= 1){
                acc.x += __shfl_xor_sync(FULL, acc.x, off);
                acc.y += __shfl_xor_sync(FULL, acc.y, off);
                acc.z += __shfl_xor_sync(FULL, acc.z, off);
                acc.w += __shfl_xor_sync(FULL, acc.w, off);
            }
            if (lane < 8){
                int f = lane*4;
                sAcc[w][f+0] = acc.x; sAcc[w][f+1] = acc.y;
                sAcc[w][f+2] = acc.z; sAcc[w][f+3] = acc.w;
            }
            __syncwarp();
            float msg = sAcc[w][lane];
            float inv = 1.f / fmaxf((float)(e1 - s), 1.f);
            float xv = (lane < DIN) ? xin[(size_t)v*DIN + lane] : 0.f;
            float rt = 0.f;
            #pragma unroll
            for (int i = 0; i < DIN; i++)
                rt = fmaf(__shfl_sync(FULL, xv, i), sR[i*32+lane], rt);
            float o = rt + msg*inv + sBi[lane];
            hout[(size_t)v*32 + lane] = o;
            accS += o;
            accQ = fmaf(o, o, accQ);
        }
    }
    atomicAdd(&ssum[lane], accS);
    atomicAdd(&ssq[lane], accQ);
    __syncthreads();
    if (t < 32){
        atomicAdd(&g_stats[LAYER*64 + t],      ssum[t]);
        atomicAdd(&g_stats[LAYER*64 + 32 + t], ssq[t]);
    }
}

// ==== single persistent mega-kernel ====
__global__ void __launch_bounds__(TPB, 1)
k_mega(const float* __restrict__ x, const float* __restrict__ attr,
       const float* __restrict__ edft, const int* __restrict__ src,
       const int* __restrict__ dst, const int* __restrict__ batch,
       const float* l0w1, const float* l0b1, const float* l0w2, const float* l0b2,
       const float* l0root, const float* l0bias, const float* l0g, const float* l0be,
       const float* l1w1, const float* l1b1, const float* l1w2, const float* l1b2,
       const float* l1root, const float* l1bias, const float* l1g, const float* l1be,
       const float* mw1, const float* mb1, const float* mw2, const float* mb2,
       float* out)
{
    __shared__ float sW0[1024], sW1[1024], sW2[1024];
    __shared__ float sSc[32], sSh[32], sBi[32], ssum[32], ssq[32];
    __shared__ float sMin[32], sMax[32];
    __shared__ float sAcc[32][64];
    int t = threadIdx.x, lane = t & 31, w = t >> 5;

    // -------- P0: zeroing (block 0) + buildAB (blocks <2NK) + edge deg/rank/minmax (all) --------
    if (blockIdx.x == 0){
        for (int i = t; i < 4*Hh; i += TPB) g_stats[i] = 0.f;
        for (int i = t; i < Gg*Hh; i += TPB) g_pool[i] = 0.f;
        if (t < Gg) g_pcnt[t] = 0;
    }
    if (blockIdx.x < 2*NK){
        int layer = (blockIdx.x >= NK);
        int k = blockIdx.x - layer*NK;
        int D = layer ? (Hh*Hh) : (D0*Hh);
        float* A = layer ? g_A1 : g_A0;
        float* B = layer ? g_B1 : g_B0;
        const float* ew1 = layer ? l1w1 : l0w1;
        const float* eb1 = layer ? l1b1 : l0b1;
        const float* ew2 = layer ? l1w2 : l0w2;
        const float* eb2 = layer ? l1b2 : l0b2;
        float* sw = sW0; float* sb = sW0 + 32; int* sr = (int*)sW1;
        if (t < 32){
            float wj = ew1[t], bj = eb1[t], tv; int r;
            rank32(wj, bj, tv, r, t);
            sw[t] = wj; sb[t] = bj; sr[t] = r;
        }
        __syncthreads();
        for (int d = t; d < D; d += TPB){
            float a = 0.f, b = eb2[d];
            for (int j = 0; j < 32; j++){
                float wj = sw[j];
                bool act = (wj > 0.f) ? (k > sr[j]) : ((wj < 0.f) ? (k <= sr[j]) : (sb[j] > 0.f));
                if (act){ float w2 = ew2[j*D+d]; a += wj*w2; b += sb[j]*w2; }
            }
            A[k*D+d] = a; B[k*D+d] = b;
        }
        __syncthreads();
    }
    {
        float amn = FLT_MAX, amx = -FLT_MAX;
        for (int e = blockIdx.x*TPB + t; e < Ee; e += gridDim.x*TPB){
            float a = attr[e];
            amn = fminf(amn, a); amx = fmaxf(amx, a);
            g_rank[e] = atomicAdd(&g_deg[dst[e]], 1);
        }
        #pragma unroll
        for (int off = 16; off; off >>= 1){
            amn = fminf(amn, __shfl_xor_sync(FULL, amn, off));
            amx = fmaxf(amx, __shfl_xor_sync(FULL, amx, off));
        }
        if (lane == 0){ sMin[w] = amn; sMax[w] = amx; }
        __syncthreads();
        if (t < 32){
            amn = sMin[t]; amx = sMax[t];
            #pragma unroll
            for (int off = 16; off; off >>= 1){
                amn = fminf(amn, __shfl_xor_sync(FULL, amn, off));
                amx = fmaxf(amx, __shfl_xor_sync(FULL, amx, off));
            }
            if (t == 0){ g_bmin[blockIdx.x] = amn; g_bmax[blockIdx.x] = amx; }
        }
    }
    gridbar(0);

    // -------- P1: segment allocation + interval-range detect --------
    if (blockIdx.x == 0 && t < 32){
        float amn = FLT_MAX, amx = -FLT_MAX;
        for (int b = lane; b < (int)gridDim.x; b += 32){
            amn = fminf(amn, g_bmin[b]); amx = fmaxf(amx, g_bmax[b]);
        }
        #pragma unroll
        for (int off = 16; off; off >>= 1){
            amn = fminf(amn, __shfl_xor_sync(FULL, amn, off));
            amx = fmaxf(amx, __shfl_xor_sync(FULL, amx, off));
        }
        float wj = l0w1[lane], bj = l0b1[lane];
        float tj = (wj != 0.f) ? (-bj/wj) : FLT_MAX;
        int kmin = __popc(__ballot_sync(FULL, tj <= amn));
        int kmax = __popc(__ballot_sync(FULL, tj <= amx));
        if (lane == 0){ g_klive[0] = kmin; g_nlive[0] = kmax - kmin + 1; }
        wj = l1w1[lane]; bj = l1b1[lane];
        tj = (wj != 0.f) ? (-bj/wj) : FLT_MAX;
        kmin = __popc(__ballot_sync(FULL, tj <= amn));
        kmax = __popc(__ballot_sync(FULL, tj <= amx));
        if (lane == 0){ g_klive[1] = kmin; g_nlive[1] = kmax - kmin + 1; }
    }
    for (int base = blockIdx.x*TPB; base < Nn; base += gridDim.x*TPB){
        int i = base + t;
        int d = (i < Nn) ? g_deg[i] : 0;
        int sc = d;
        #pragma unroll
        for (int off = 1; off < 32; off <<= 1){
            int y = __shfl_up_sync(FULL, sc, off);
            if (lane >= off) sc += y;
        }
        int tot = __shfl_sync(FULL, sc, 31);
        int base2 = 0;
        if (lane == 31 && tot) base2 = atomicAdd(&g_total, tot);
        base2 = __shfl_sync(FULL, base2, 31);
        if (i < Nn){
            int my = base2 + sc - d;
            g_off[i] = my; g_end[i] = my + d;
            g_deg[i] = 0;
        }
    }
    gridbar(1);

    int nl0 = g_nlive[0], kl0 = g_klive[0];
    int nl1 = g_nlive[1], kl1 = g_klive[1];
    bool fastboth = (nl0 == 1) && (nl1 == 1);

    // -------- P2: CSR fill (rank-based, no atomics) + PQ0 (general) --------
    if (!fastboth){
        float* st0 = sW0; float* st1 = sW0 + 32;
        if (t < 32){ float tv; int r; rank32(l0w1[t], l0b1[t], tv, r, t); st0[r] = tv; }
        else if (t < 64){ int j = t-32; float tv; int r; rank32(l1w1[j], l1b1[j], tv, r, j); st1[r] = tv; }
        __syncthreads();
    }
    for (int e = blockIdx.x*TPB + t; e < Ee; e += gridDim.x*TPB){
        float a = attr[e];
        unsigned px = (unsigned)src[e];
        if (!fastboth){
            const float* st0 = sW0; const float* st1 = sW0 + 32;
            int k0 = 0, k1 = 0;
            #pragma unroll
            for (int step = 16; step > 0; step >>= 1){
                if (st0[k0 + step - 1] <= a) k0 += step;
                if (st1[k1 + step - 1] <= a) k1 += step;
            }
            k0 += (st0[k0] <= a);
            k1 += (st1[k1] <= a);
            px |= ((unsigned)k0 << 16) | ((unsigned)k1 << 24);
        }
        uint2 pl; pl.x = px; pl.y = __float_as_uint(a);
        int p = g_off[dst[e]] + g_rank[e];
        g_ebuf[p] = pl;
    }
    if (nl0 > 1){
        for (int u = blockIdx.x*32 + w; u < Nn; u += gridDim.x*32){
            float xv_l = (lane < D0) ? __ldg(x + (size_t)u*D0 + lane) : 0.f;
            for (int k = kl0; k < kl0 + nl0; k++){
                float p = 0.f, q = 0.f;
                for (int i = 0; i < D0; i++){
                    float xv = __shfl_sync(FULL, xv_l, i);
                    p = fmaf(xv, g_A0[k*D0*Hh + i*Hh + lane], p);
                    q = fmaf(xv, g_B0[k*D0*Hh + i*Hh + lane], q);
                }
                size_t ro = ((size_t)(k*Nn + u))*64;
                g_PQ[ro + lane] = p;
                g_PQ[ro + 32 + lane] = q;
            }
        }
    }
    gridbar(2);

    // -------- P3: aggregation layer 0 --------
    agg_phase<D0,0>(x, l0root, l0bias, g_h,
                    sW0, sW1, sW2, sBi, ssum, ssq, sAcc, nl0, kl0);
    gridbar(3);

    // -------- P3a: hn = relu(BN0(h)) once --------
    __syncthreads();
    if (t < 32){
        float mu  = __ldcg(&g_stats[t])    * (1.f/(float)Nn);
        float var = __ldcg(&g_stats[32+t]) * (1.f/(float)Nn) - mu*mu;
        float sc  = rsqrtf(var + EPSI) * __ldg(l0g + t);
        sSc[t] = sc;
        sSh[t] = __ldg(l0be + t) - mu*sc;
    }
    __syncthreads();
    for (int idx = blockIdx.x*TPB + t; idx < Nn*Hh; idx += gridDim.x*TPB){
        int f = idx & 31;
        g_hn[idx] = fmaxf(g_h[idx]*sSc[f] + sSh[f], 0.f);
    }
    gridbar(4);
    if (nl1 > 1){
        for (int u = blockIdx.x*32 + w; u < Nn; u += gridDim.x*32){
            float xv_l = g_hn[(size_t)u*32 + lane];
            for (int k = kl1; k < kl1 + nl1; k++){
                float p = 0.f, q = 0.f;
                for (int i = 0; i < Hh; i++){
                    float xv = __shfl_sync(FULL, xv_l, i);
                    p = fmaf(xv, g_A1[k*Hh*Hh + i*Hh + lane], p);
                    q = fmaf(xv, g_B1[k*Hh*Hh + i*Hh + lane], q);
                }
                size_t ro = ((size_t)(k*Nn + u))*64;
                g_PQ[ro + lane] = p;
                g_PQ[ro + 32 + lane] = q;
            }
        }
        gridbar(5);
    }

    // -------- P4: aggregation layer 1 --------
    agg_phase<Hh,1>(g_hn, l1root, l1bias, g_h,
                    sW0, sW1, sW2, sBi, ssum, ssq, sAcc, nl1, kl1);
    gridbar(6);

    // -------- P5: BN1 + ReLU + pool --------
    __syncthreads();
    if (t < 32){
        float mu  = __ldcg(&g_stats[64+t]) * (1.f/(float)Nn);
        float var = __ldcg(&g_stats[96+t]) * (1.f/(float)Nn) - mu*mu;
        float sc  = rsqrtf(var + EPSI) * __ldg(l1g + t);
        sSc[t] = sc;
        sSh[t] = __ldg(l1be + t) - mu*sc;
    }
    __syncthreads();
    for (int idx = blockIdx.x*TPB + t; idx < Nn*Hh; idx += gridDim.x*TPB){
        int f = idx & 31, v = idx >> 5;
        float xv = fmaxf(g_h[idx]*sSc[f] + sSh[f], 0.f);
        int g = batch[v];
        atomicAdd(&g_pool[g*Hh + f], xv);
        if (f == 0) atomicAdd(&g_pcnt[g], 1);
    }
    gridbar(7);

    // -------- P6: readout MLP + cleanup (block 0) --------
    if (blockIdx.x == 0){
        if (t == TPB-1) g_total = 0;
        if (t < Gg){
            float zin[Hh+1];
            float inv = 1.f / fmaxf((float)__ldcg(&g_pcnt[t]), 1.f);
            for (int i = 0; i < Hh; i++) zin[i] = __ldcg(&g_pool[t*Hh+i])*inv;
            zin[Hh] = edft[t];
            float o = mb2[0];
            for (int j = 0; j < 64; j++){
                float hsum = mb1[j];
                #pragma unroll
                for (int i = 0; i < Hh+1; i++) hsum = fmaf(zin[i], mw1[i*64+j], hsum);
                o = fmaf(fmaxf(hsum, 0.f), mw2[j], o);
            }
            out[t] = o;
        }
    }
}

extern "C" void kernel_launch(void* const* d_in, const int* in_sizes, int n_in,
                              void* d_out, int out_size){
    const float* x     = (const float*)d_in[0];
    const float* attr  = (const float*)d_in[1];
    const float* edft  = (const float*)d_in[2];
    const int*   src   = (const int*)  d_in[3];
    const int*   dst   = (const int*)  d_in[4];
    const int*   batch = (const int*)  d_in[5];
    const float* l0w1=(const float*)d_in[6],  *l0b1=(const float*)d_in[7];
    const float* l0w2=(const float*)d_in[8],  *l0b2=(const float*)d_in[9];
    const float* l0root=(const float*)d_in[10],*l0bias=(const float*)d_in[11];
    const float* l0g=(const float*)d_in[12],  *l0be=(const float*)d_in[13];
    const float* l1w1=(const float*)d_in[14], *l1b1=(const float*)d_in[15];
    const float* l1w2=(const float*)d_in[16], *l1b2=(const float*)d_in[17];
    const float* l1root=(const float*)d_in[18],*l1bias=(const float*)d_in[19];
    const float* l1g=(const float*)d_in[20],  *l1be=(const float*)d_in[21];
    const float* mw1=(const float*)d_in[22],  *mb1=(const float*)d_in[23];
    const float* mw2=(const float*)d_in[24],  *mb2=(const float*)d_in[25];
    float* out = (float*)d_out;

    int dev = 0;
    cudaGetDevice(&dev);
    int nsm = 0;
    cudaDeviceGetAttribute(&nsm, cudaDevAttrMultiProcessorCount, dev);
    if (nsm <= 0) nsm = 148;
    int nb = 0;
    cudaOccupancyMaxActiveBlocksPerMultiprocessor(&nb, k_mega, TPB, 0);
    if (nb < 1) nb = 1;
    int grid = nsm * nb;
    if (grid > 1024) grid = 1024;

    k_mega<<<grid, TPB>>>(x, attr, edft, src, dst, batch,
                          l0w1, l0b1, l0w2, l0b2, l0root, l0bias, l0g, l0be,
                          l1w1, l1b1, l1w2, l1b2, l1root, l1bias, l1g, l1be,
                          mw1, mb1, mw2, mb2, out);
}